// round 5
// baseline (speedup 1.0000x reference)
#include <cuda_runtime.h>
#include <math.h>
#include <stdint.h>

// ---------------- problem constants ----------------
namespace {
constexpr int kB  = 4;
constexpr int kN  = 1024;
constexpr int kD  = 768;
constexpr int kH  = 12;
constexpr int kHD = 64;
constexpr int kGP = 49;
constexpr int kMLP = 3072;
constexpr int kT  = kB * kN;     // 4096 tokens
constexpr int kBH = kB * kH;     // 48 batched heads
constexpr int kQD = 3 * kD;      // 2304
}

// ---------------- scratch (device globals: no allocation allowed) ----------------
__device__ float g_xn [kT * kD];
__device__ float g_qkv[kT * kQD];
__device__ float g_S  [(size_t)kBH * kN * kN];   // final mixed attn A
__device__ float g_G  [(size_t)kBH * kN * kN];   // gw @ gw^T
__device__ float g_gw [kBH * kN * 64];           // softmaxed group weights, padded 49->64
__device__ float g_inv[kBH * kN];                // 1/(colsum+eps)
__device__ float g_ctx[kT * kD];                 // merged-head attention output
__device__ float g_y  [kT * kD];                 // after proj residual
__device__ float g_yn [kT * kD];
__device__ float g_hdn[kT * kMLP];

__device__ __forceinline__ float gelu_exact(float x) {
    return 0.5f * x * (1.0f + erff(x * 0.70710678118654752440f));
}

__device__ __forceinline__ uint32_t f2tf32(float x) {
    uint32_t r;
    asm("cvt.rna.tf32.f32 %0, %1;" : "=r"(r) : "f"(x));
    return r;
}

// D += A(m16k8,row) * B(k8n8,col)   tf32
__device__ __forceinline__ void mma8(float* c, const uint32_t* a, const uint32_t* b) {
    asm volatile("mma.sync.aligned.m16n8k8.row.col.f32.tf32.tf32.f32 "
                 "{%0,%1,%2,%3}, {%4,%5,%6,%7}, {%8,%9}, {%0,%1,%2,%3};"
                 : "+f"(c[0]), "+f"(c[1]), "+f"(c[2]), "+f"(c[3])
                 : "r"(a[0]), "r"(a[1]), "r"(a[2]), "r"(a[3]),
                   "r"(b[0]), "r"(b[1]));
}

// ---------------- LayerNorm: one block (256 thr) per row of 768 ----------------
__global__ __launch_bounds__(256) void ln_kernel(const float* __restrict__ x,
                                                 const float* __restrict__ w,
                                                 const float* __restrict__ b,
                                                 float* __restrict__ out) {
    __shared__ float sh1[8], sh2[8];
    int row = blockIdx.x;
    int t = threadIdx.x;
    const float* xr = x + (size_t)row * kD;
    float v[3];
    float s = 0.f, s2 = 0.f;
#pragma unroll
    for (int i = 0; i < 3; i++) {
        v[i] = xr[t + i * 256];
        s  += v[i];
        s2 += v[i] * v[i];
    }
#pragma unroll
    for (int o = 16; o; o >>= 1) {
        s  += __shfl_xor_sync(0xffffffffu, s, o);
        s2 += __shfl_xor_sync(0xffffffffu, s2, o);
    }
    if ((t & 31) == 0) { sh1[t >> 5] = s; sh2[t >> 5] = s2; }
    __syncthreads();
    s = sh1[t & 7]; s2 = sh2[t & 7];
#pragma unroll
    for (int o = 4; o; o >>= 1) {
        s  += __shfl_xor_sync(0xffffffffu, s, o);
        s2 += __shfl_xor_sync(0xffffffffu, s2, o);
    }
    float mu   = s * (1.0f / kD);
    float var  = fmaxf(s2 * (1.0f / kD) - mu * mu, 0.f);
    float rstd = rsqrtf(var + 1e-5f);
    float* orow = out + (size_t)row * kD;
#pragma unroll
    for (int i = 0; i < 3; i++) {
        int c = t + i * 256;
        orow[c] = (v[i] - mu) * rstd * w[c] + b[c];
    }
}

// ------- TF32 dense GEMM (NN): C[M,N] = A[M,K] @ B[K,N] + bias (+gelu)(+res) --
// 128x128 block, 8 warps (4m x 2n), warp m32 x n64, K-step 16, reg-prefetch DB.
__global__ __launch_bounds__(256) void gemm_nn_tf32(
        const float* __restrict__ A, const float* __restrict__ B,
        const float* __restrict__ bias, const float* __restrict__ res,
        float* __restrict__ C, int M, int N, int K, int act) {
    __shared__ uint32_t As[128][20];   // [m][k]
    __shared__ uint32_t Bs[16][136];   // [k][n]
    int tid = threadIdx.x, lane = tid & 31, warp = tid >> 5;
    int g = lane >> 2, tg = lane & 3;
    int wm = (warp >> 1) * 32, wn = (warp & 1) * 64;
    int row0 = blockIdx.y * 128, col0 = blockIdx.x * 128;
    int ra = tid >> 2, ca = (tid & 3) * 4;       // A loader coords
    int kb = tid >> 5, nb = (tid & 31) * 4;      // B loader coords
    const float* Abase = A + (size_t)(row0 + ra) * K + ca;
    const float* Abase2 = A + (size_t)(row0 + ra + 64) * K + ca;
    const float* Bbase = B + (size_t)kb * N + col0 + nb;
    const float* Bbase2 = B + (size_t)(kb + 8) * N + col0 + nb;
    float acc[2][8][4] = {};
    float4 pa0 = *(const float4*)(Abase);
    float4 pa1 = *(const float4*)(Abase2);
    float4 pb0 = *(const float4*)(Bbase);
    float4 pb1 = *(const float4*)(Bbase2);
    for (int k0 = 0; k0 < K; k0 += 16) {
        As[ra][ca + 0] = f2tf32(pa0.x); As[ra][ca + 1] = f2tf32(pa0.y);
        As[ra][ca + 2] = f2tf32(pa0.z); As[ra][ca + 3] = f2tf32(pa0.w);
        As[ra + 64][ca + 0] = f2tf32(pa1.x); As[ra + 64][ca + 1] = f2tf32(pa1.y);
        As[ra + 64][ca + 2] = f2tf32(pa1.z); As[ra + 64][ca + 3] = f2tf32(pa1.w);
        Bs[kb][nb + 0] = f2tf32(pb0.x); Bs[kb][nb + 1] = f2tf32(pb0.y);
        Bs[kb][nb + 2] = f2tf32(pb0.z); Bs[kb][nb + 3] = f2tf32(pb0.w);
        Bs[kb + 8][nb + 0] = f2tf32(pb1.x); Bs[kb + 8][nb + 1] = f2tf32(pb1.y);
        Bs[kb + 8][nb + 2] = f2tf32(pb1.z); Bs[kb + 8][nb + 3] = f2tf32(pb1.w);
        __syncthreads();
        if (k0 + 16 < K) {     // prefetch next tiles: overlaps with mma below
            pa0 = *(const float4*)(Abase + k0 + 16);
            pa1 = *(const float4*)(Abase2 + k0 + 16);
            pb0 = *(const float4*)(Bbase + (size_t)(k0 + 16) * N);
            pb1 = *(const float4*)(Bbase2 + (size_t)(k0 + 16) * N);
        }
#pragma unroll
        for (int k8 = 0; k8 < 16; k8 += 8) {
            uint32_t af[2][4], bf[8][2];
#pragma unroll
            for (int mi = 0; mi < 2; mi++) {
                int r = wm + mi * 16 + g;
                af[mi][0] = As[r][k8 + tg];
                af[mi][1] = As[r + 8][k8 + tg];
                af[mi][2] = As[r][k8 + tg + 4];
                af[mi][3] = As[r + 8][k8 + tg + 4];
            }
#pragma unroll
            for (int nj = 0; nj < 8; nj++) {
                int n = wn + nj * 8 + g;
                bf[nj][0] = Bs[k8 + tg][n];
                bf[nj][1] = Bs[k8 + tg + 4][n];
            }
#pragma unroll
            for (int mi = 0; mi < 2; mi++)
#pragma unroll
                for (int nj = 0; nj < 8; nj++)
                    mma8(acc[mi][nj], af[mi], bf[nj]);
        }
        __syncthreads();
    }
#pragma unroll
    for (int mi = 0; mi < 2; mi++) {
#pragma unroll
        for (int nj = 0; nj < 8; nj++) {
            int r0 = row0 + wm + mi * 16 + g;
            int c = col0 + wn + nj * 8 + tg * 2;
            float b0 = bias[c], b1 = bias[c + 1];
            float o00 = acc[mi][nj][0] + b0, o01 = acc[mi][nj][1] + b1;
            float o10 = acc[mi][nj][2] + b0, o11 = acc[mi][nj][3] + b1;
            if (act) {
                o00 = gelu_exact(o00); o01 = gelu_exact(o01);
                o10 = gelu_exact(o10); o11 = gelu_exact(o11);
            }
            if (res) {
                o00 += res[(size_t)r0 * N + c];       o01 += res[(size_t)r0 * N + c + 1];
                o10 += res[(size_t)(r0 + 8) * N + c]; o11 += res[(size_t)(r0 + 8) * N + c + 1];
            }
            *(float2*)&C[(size_t)r0 * N + c]       = make_float2(o00, o01);
            *(float2*)&C[(size_t)(r0 + 8) * N + c] = make_float2(o10, o11);
        }
    }
}

// ---- FUSED: A = (1-a)*softmax(scale*QK^T * G) + a*G for a 16-row strip -------
// Block: 16 rows x full 1024 cols. Q frags in regs, K streamed via smem.
__global__ __launch_bounds__(256) void score_mix_tf32(
        const float* __restrict__ qkv, const float* __restrict__ G,
        const float* __restrict__ alpha, float* __restrict__ Aout) {
    __shared__ uint32_t Ks[128][20];
    __shared__ uint32_t Qf[16][20];
    __shared__ float red[16][8];
    int bh = blockIdx.y, b = bh / kH, h = bh % kH;
    int n0 = blockIdx.x * 16;
    const float* qb = qkv + (size_t)b * kN * kQD + h * kHD;
    const float* kbp = qb + kD;
    const float* Gb = G + (size_t)bh * kN * kN;
    float* Ab = Aout + (size_t)bh * kN * kN;
    int tid = threadIdx.x, lane = tid & 31, warp = tid >> 5;
    int g = lane >> 2, tg = lane & 3;
    float a_sig = 1.f / (1.f + __expf(-alpha[h]));

    // load Q strip (16 x 64), scale folded (exact /8)
    {
        int r = tid >> 4, c4 = (tid & 15) * 4;
        float4 qv = *(const float4*)(qb + (size_t)(n0 + r) * kQD + c4);
        Qf[r][c4 + 0] = f2tf32(qv.x * 0.125f); Qf[r][c4 + 1] = f2tf32(qv.y * 0.125f);
        Qf[r][c4 + 2] = f2tf32(qv.z * 0.125f); Qf[r][c4 + 3] = f2tf32(qv.w * 0.125f);
    }
    __syncthreads();
    uint32_t af[8][4];
#pragma unroll
    for (int k8 = 0; k8 < 8; k8++) {
        af[k8][0] = Qf[g][k8 * 8 + tg];
        af[k8][1] = Qf[g + 8][k8 * 8 + tg];
        af[k8][2] = Qf[g][k8 * 8 + tg + 4];
        af[k8][3] = Qf[g + 8][k8 * 8 + tg + 4];
    }

    float acc[8][2][4] = {};
    for (int ct = 0; ct < 8; ct++) {
        int m0 = ct * 128;
        __syncthreads();
#pragma unroll
        for (int i = 0; i < 8; i++) {
            int idx = tid + i * 256;           // 2048 float4s: 128 rows x 16
            int r = idx >> 4, c4 = (idx & 15) * 4;
            float4 kv = *(const float4*)(kbp + (size_t)(m0 + r) * kQD + c4);
            Ks[r][c4 + 0] = f2tf32(kv.x); Ks[r][c4 + 1] = f2tf32(kv.y);
            Ks[r][c4 + 2] = f2tf32(kv.z); Ks[r][c4 + 3] = f2tf32(kv.w);
        }
        __syncthreads();
#pragma unroll
        for (int k8 = 0; k8 < 8; k8++) {
            uint32_t bf[2][2];
#pragma unroll
            for (int nj = 0; nj < 2; nj++) {
                int n = warp * 16 + nj * 8 + g;
                bf[nj][0] = Ks[n][k8 * 8 + tg];
                bf[nj][1] = Ks[n][k8 * 8 + tg + 4];
            }
            mma8(acc[ct][0], af[k8], bf[0]);
            mma8(acc[ct][1], af[k8], bf[1]);
        }
    }

    // t = s * g ; track per-row maxima (rows g and g+8 of the strip)
    float mx0 = -1e30f, mx1 = -1e30f;
#pragma unroll
    for (int ct = 0; ct < 8; ct++)
#pragma unroll
        for (int nj = 0; nj < 2; nj++) {
            int c = ct * 128 + warp * 16 + nj * 8 + tg * 2;
            float2 gv0 = *(const float2*)&Gb[(size_t)(n0 + g) * kN + c];
            float2 gv1 = *(const float2*)&Gb[(size_t)(n0 + g + 8) * kN + c];
            acc[ct][nj][0] *= gv0.x; acc[ct][nj][1] *= gv0.y;
            acc[ct][nj][2] *= gv1.x; acc[ct][nj][3] *= gv1.y;
            mx0 = fmaxf(mx0, fmaxf(acc[ct][nj][0], acc[ct][nj][1]));
            mx1 = fmaxf(mx1, fmaxf(acc[ct][nj][2], acc[ct][nj][3]));
        }
    mx0 = fmaxf(mx0, __shfl_xor_sync(0xffffffffu, mx0, 1));
    mx0 = fmaxf(mx0, __shfl_xor_sync(0xffffffffu, mx0, 2));
    mx1 = fmaxf(mx1, __shfl_xor_sync(0xffffffffu, mx1, 1));
    mx1 = fmaxf(mx1, __shfl_xor_sync(0xffffffffu, mx1, 2));
    __syncthreads();
    if (tg == 0) { red[g][warp] = mx0; red[g + 8][warp] = mx1; }
    __syncthreads();
    mx0 = red[g][0]; mx1 = red[g + 8][0];
#pragma unroll
    for (int w = 1; w < 8; w++) {
        mx0 = fmaxf(mx0, red[g][w]);
        mx1 = fmaxf(mx1, red[g + 8][w]);
    }
    __syncthreads();
    // exp + row sums
    float sum0 = 0.f, sum1 = 0.f;
#pragma unroll
    for (int ct = 0; ct < 8; ct++)
#pragma unroll
        for (int nj = 0; nj < 2; nj++) {
            acc[ct][nj][0] = __expf(acc[ct][nj][0] - mx0);
            acc[ct][nj][1] = __expf(acc[ct][nj][1] - mx0);
            acc[ct][nj][2] = __expf(acc[ct][nj][2] - mx1);
            acc[ct][nj][3] = __expf(acc[ct][nj][3] - mx1);
            sum0 += acc[ct][nj][0] + acc[ct][nj][1];
            sum1 += acc[ct][nj][2] + acc[ct][nj][3];
        }
    sum0 += __shfl_xor_sync(0xffffffffu, sum0, 1);
    sum0 += __shfl_xor_sync(0xffffffffu, sum0, 2);
    sum1 += __shfl_xor_sync(0xffffffffu, sum1, 1);
    sum1 += __shfl_xor_sync(0xffffffffu, sum1, 2);
    if (tg == 0) { red[g][warp] = sum0; red[g + 8][warp] = sum1; }
    __syncthreads();
    sum0 = 0.f; sum1 = 0.f;
#pragma unroll
    for (int w = 0; w < 8; w++) { sum0 += red[g][w]; sum1 += red[g + 8][w]; }
    float is0 = (1.f - a_sig) / sum0;
    float is1 = (1.f - a_sig) / sum1;
    // mix with G (second read: L2-hot) and store A
#pragma unroll
    for (int ct = 0; ct < 8; ct++)
#pragma unroll
        for (int nj = 0; nj < 2; nj++) {
            int c = ct * 128 + warp * 16 + nj * 8 + tg * 2;
            float2 gv0 = *(const float2*)&Gb[(size_t)(n0 + g) * kN + c];
            float2 gv1 = *(const float2*)&Gb[(size_t)(n0 + g + 8) * kN + c];
            float2 o0 = make_float2(acc[ct][nj][0] * is0 + a_sig * gv0.x,
                                    acc[ct][nj][1] * is0 + a_sig * gv0.y);
            float2 o1 = make_float2(acc[ct][nj][2] * is1 + a_sig * gv1.x,
                                    acc[ct][nj][3] * is1 + a_sig * gv1.y);
            *(float2*)&Ab[(size_t)(n0 + g) * kN + c] = o0;
            *(float2*)&Ab[(size_t)(n0 + g + 8) * kN + c] = o1;
        }
}

// ---------------- G = gw @ gw^T (NT), tf32, K=64 padded ----------------
__global__ __launch_bounds__(256) void gmat_tf32(const float* __restrict__ gw,
                                                 float* __restrict__ G) {
    __shared__ uint32_t As[128][20];
    __shared__ uint32_t Bs[128][20];
    int bh = blockIdx.z;
    const float* gb = gw + (size_t)bh * kN * 64;
    int tid = threadIdx.x, lane = tid & 31, warp = tid >> 5;
    int g = lane >> 2, tg = lane & 3;
    int wm = (warp >> 1) * 32, wn = (warp & 1) * 64;
    int n0 = blockIdx.y * 128, m0 = blockIdx.x * 128;
    float acc[2][8][4] = {};
    for (int k0 = 0; k0 < 64; k0 += 16) {
#pragma unroll
        for (int i = 0; i < 2; i++) {
            int idx = tid + i * 256;
            int r = idx >> 2, c4 = (idx & 3) * 4;
            float4 av = *(const float4*)(gb + (size_t)(n0 + r) * 64 + k0 + c4);
            float4 bv = *(const float4*)(gb + (size_t)(m0 + r) * 64 + k0 + c4);
            As[r][c4 + 0] = f2tf32(av.x); As[r][c4 + 1] = f2tf32(av.y);
            As[r][c4 + 2] = f2tf32(av.z); As[r][c4 + 3] = f2tf32(av.w);
            Bs[r][c4 + 0] = f2tf32(bv.x); Bs[r][c4 + 1] = f2tf32(bv.y);
            Bs[r][c4 + 2] = f2tf32(bv.z); Bs[r][c4 + 3] = f2tf32(bv.w);
        }
        __syncthreads();
#pragma unroll
        for (int k8 = 0; k8 < 16; k8 += 8) {
            uint32_t af[2][4], bf[8][2];
#pragma unroll
            for (int mi = 0; mi < 2; mi++) {
                int r = wm + mi * 16 + g;
                af[mi][0] = As[r][k8 + tg];
                af[mi][1] = As[r + 8][k8 + tg];
                af[mi][2] = As[r][k8 + tg + 4];
                af[mi][3] = As[r + 8][k8 + tg + 4];
            }
#pragma unroll
            for (int nj = 0; nj < 8; nj++) {
                int n = wn + nj * 8 + g;
                bf[nj][0] = Bs[n][k8 + tg];
                bf[nj][1] = Bs[n][k8 + tg + 4];
            }
#pragma unroll
            for (int mi = 0; mi < 2; mi++)
#pragma unroll
                for (int nj = 0; nj < 8; nj++)
                    mma8(acc[mi][nj], af[mi], bf[nj]);
        }
        __syncthreads();
    }
    float* Gb = G + (size_t)bh * kN * kN;
#pragma unroll
    for (int mi = 0; mi < 2; mi++) {
#pragma unroll
        for (int nj = 0; nj < 8; nj++) {
            int r0 = n0 + wm + mi * 16 + g;
            int c = m0 + wn + nj * 8 + tg * 2;
            *(float2*)&Gb[(size_t)r0 * kN + c] =
                make_float2(acc[mi][nj][0], acc[mi][nj][1]);
            *(float2*)&Gb[(size_t)(r0 + 8) * kN + c] =
                make_float2(acc[mi][nj][2], acc[mi][nj][3]);
        }
    }
}

// ------- out = (A * inv[k]) @ V  (NN), tf32; heads merged into ctx ------------
__global__ __launch_bounds__(256) void av_tf32(const float* __restrict__ Sa,
                                               const float* __restrict__ inv,
                                               const float* __restrict__ qkv,
                                               float* __restrict__ ctx) {
    __shared__ uint32_t As[128][20];
    __shared__ uint32_t Bs[16][72];
    int bh = blockIdx.z, b = bh / kH, h = bh % kH;
    const float* Ab = Sa + (size_t)bh * kN * kN;
    const float* vb = qkv + (size_t)b * kN * kQD + 2 * kD + h * kHD;
    const float* invb = inv + bh * kN;
    int tid = threadIdx.x, lane = tid & 31, warp = tid >> 5;
    int g = lane >> 2, tg = lane & 3;
    int wm = (warp >> 1) * 32, wn = (warp & 1) * 32;
    int row0 = blockIdx.y * 128;
    float acc[2][4][4] = {};
    for (int k0 = 0; k0 < kN; k0 += 16) {
#pragma unroll
        for (int i = 0; i < 2; i++) {
            int idx = tid + i * 256;
            int r = idx >> 2, c4 = (idx & 3) * 4;
            float4 v = *(const float4*)(Ab + (size_t)(row0 + r) * kN + k0 + c4);
            As[r][c4 + 0] = f2tf32(v.x); As[r][c4 + 1] = f2tf32(v.y);
            As[r][c4 + 2] = f2tf32(v.z); As[r][c4 + 3] = f2tf32(v.w);
        }
        {
            int kr = tid >> 4, nc = (tid & 15) * 4;
            float iv = invb[k0 + kr];
            float4 v = *(const float4*)(vb + (size_t)(k0 + kr) * kQD + nc);
            Bs[kr][nc + 0] = f2tf32(v.x * iv); Bs[kr][nc + 1] = f2tf32(v.y * iv);
            Bs[kr][nc + 2] = f2tf32(v.z * iv); Bs[kr][nc + 3] = f2tf32(v.w * iv);
        }
        __syncthreads();
#pragma unroll
        for (int k8 = 0; k8 < 16; k8 += 8) {
            uint32_t af[2][4], bf[4][2];
#pragma unroll
            for (int mi = 0; mi < 2; mi++) {
                int r = wm + mi * 16 + g;
                af[mi][0] = As[r][k8 + tg];
                af[mi][1] = As[r + 8][k8 + tg];
                af[mi][2] = As[r][k8 + tg + 4];
                af[mi][3] = As[r + 8][k8 + tg + 4];
            }
#pragma unroll
            for (int nj = 0; nj < 4; nj++) {
                int n = wn + nj * 8 + g;
                bf[nj][0] = Bs[k8 + tg][n];
                bf[nj][1] = Bs[k8 + tg + 4][n];
            }
#pragma unroll
            for (int mi = 0; mi < 2; mi++)
#pragma unroll
                for (int nj = 0; nj < 4; nj++)
                    mma8(acc[mi][nj], af[mi], bf[nj]);
        }
        __syncthreads();
    }
#pragma unroll
    for (int mi = 0; mi < 2; mi++) {
#pragma unroll
        for (int nj = 0; nj < 4; nj++) {
            int tok0 = b * kN + row0 + wm + mi * 16 + g;
            int c = h * kHD + wn + nj * 8 + tg * 2;
            *(float2*)&ctx[(size_t)tok0 * kD + c] =
                make_float2(acc[mi][nj][0], acc[mi][nj][1]);
            *(float2*)&ctx[(size_t)(tok0 + 8) * kD + c] =
                make_float2(acc[mi][nj][2], acc[mi][nj][3]);
        }
    }
}

// ---- group weights: gw = softmax(gelu(V @ gp^T)) padded to 64 ----
__global__ __launch_bounds__(256) void gw_kernel(const float* __restrict__ qkv,
                                                 const float* __restrict__ gp_w,
                                                 float* __restrict__ gw) {
    __shared__ __align__(16) float gps[kGP][68];
    __shared__ __align__(16) float Vs[64][68];
    int bh = blockIdx.y;
    int b = bh / kH, h = bh % kH;
    int n0 = blockIdx.x * 64;
    int tid = threadIdx.x;
    const float* gph = gp_w + (size_t)h * kGP * kHD;
    for (int i = tid; i < kGP * 16; i += 256) {
        int r = i >> 4, c4 = (i & 15) * 4;
        *(float4*)&gps[r][c4] = *(const float4*)(gph + r * kHD + c4);
    }
    const float* vb = qkv + (size_t)(b * kN + n0) * kQD + 2 * kD + h * kHD;
    for (int i = tid; i < 64 * 16; i += 256) {
        int r = i >> 4, c4 = (i & 15) * 4;
        *(float4*)&Vs[r][c4] = *(const float4*)(vb + (size_t)r * kQD + c4);
    }
    __syncthreads();
    int r = tid >> 2;
    int c0 = tid & 3;
    float val[13];
    float mx = -1e30f;
#pragma unroll
    for (int j = 0; j < 13; j++) {
        int c = c0 + 4 * j;
        float acc = 0.f;
        if (c < kGP) {
#pragma unroll
            for (int d = 0; d < kHD; d += 4) {
                float4 vv = *(const float4*)&Vs[r][d];
                float4 gg = *(const float4*)&gps[c][d];
                acc += vv.x * gg.x + vv.y * gg.y + vv.z * gg.z + vv.w * gg.w;
            }
            acc = gelu_exact(acc);
            mx = fmaxf(mx, acc);
        }
        val[j] = acc;
    }
    mx = fmaxf(mx, __shfl_xor_sync(0xffffffffu, mx, 1));
    mx = fmaxf(mx, __shfl_xor_sync(0xffffffffu, mx, 2));
    float sum = 0.f;
#pragma unroll
    for (int j = 0; j < 13; j++) {
        int c = c0 + 4 * j;
        val[j] = (c < kGP) ? __expf(val[j] - mx) : 0.f;
        sum += val[j];
    }
    sum += __shfl_xor_sync(0xffffffffu, sum, 1);
    sum += __shfl_xor_sync(0xffffffffu, sum, 2);
    float is = 1.f / sum;
    float* grow = gw + (size_t)(bh * kN + n0 + r) * 64;
#pragma unroll
    for (int j = 0; j < 16; j++) {
        int c = c0 + 4 * j;
        if (c < 64) grow[c] = (j < 13 && c < kGP) ? val[j] * is : 0.f;
    }
}

// ------- column sums over n (axis=2), stores 1/(sum+1e-8) -------
__global__ __launch_bounds__(256) void colsum_kernel(const float* __restrict__ Sa,
                                                     float* __restrict__ inv) {
    int idx = blockIdx.x * 256 + threadIdx.x;   // bh*N + m
    int bh = idx >> 10, m = idx & 1023;
    const float* p = Sa + (size_t)bh * kN * kN + m;
    float s = 0.f;
#pragma unroll 4
    for (int n = 0; n < kN; n++) s += p[(size_t)n * kN];
    inv[idx] = 1.f / (s + 1e-8f);
}

// ---------------- launch ----------------
extern "C" void kernel_launch(void* const* d_in, const int* in_sizes, int n_in,
                              void* d_out, int out_size) {
    const float* x      = (const float*)d_in[0];
    const float* ln1_w  = (const float*)d_in[1];
    const float* ln1_b  = (const float*)d_in[2];
    const float* qkv_w  = (const float*)d_in[3];
    const float* qkv_b  = (const float*)d_in[4];
    const float* proj_w = (const float*)d_in[5];
    const float* proj_b = (const float*)d_in[6];
    const float* gp_w   = (const float*)d_in[7];
    const float* alpha  = (const float*)d_in[8];
    const float* ln2_w  = (const float*)d_in[9];
    const float* ln2_b  = (const float*)d_in[10];
    const float* ff1_w  = (const float*)d_in[11];
    const float* ff1_b  = (const float*)d_in[12];
    const float* ff2_w  = (const float*)d_in[13];
    const float* ff2_b  = (const float*)d_in[14];
    float* out = (float*)d_out;

    float *xn, *qkv, *S, *G, *gw, *inv, *ctx, *y, *yn, *hdn;
    cudaGetSymbolAddress((void**)&xn,  g_xn);
    cudaGetSymbolAddress((void**)&qkv, g_qkv);
    cudaGetSymbolAddress((void**)&S,   g_S);
    cudaGetSymbolAddress((void**)&G,   g_G);
    cudaGetSymbolAddress((void**)&gw,  g_gw);
    cudaGetSymbolAddress((void**)&inv, g_inv);
    cudaGetSymbolAddress((void**)&ctx, g_ctx);
    cudaGetSymbolAddress((void**)&y,   g_y);
    cudaGetSymbolAddress((void**)&yn,  g_yn);
    cudaGetSymbolAddress((void**)&hdn, g_hdn);

    // attention branch
    ln_kernel<<<kT, 256>>>(x, ln1_w, ln1_b, xn);
    gemm_nn_tf32<<<dim3(kQD / 128, kT / 128), 256>>>(xn, qkv_w, qkv_b, nullptr,
                                                     qkv, kT, kQD, kD, 0);
    gw_kernel<<<dim3(kN / 64, kBH), 256>>>(qkv, gp_w, gw);
    gmat_tf32<<<dim3(8, 8, kBH), 256>>>(gw, G);
    score_mix_tf32<<<dim3(kN / 16, kBH), 256>>>(qkv, G, alpha, S);
    colsum_kernel<<<kBH * kN / 256, 256>>>(S, inv);
    av_tf32<<<dim3(1, 8, kBH), 256>>>(S, inv, qkv, ctx);
    gemm_nn_tf32<<<dim3(kD / 128, kT / 128), 256>>>(ctx, proj_w, proj_b, x, y,
                                                    kT, kD, kD, 0);
    // FFN branch
    ln_kernel<<<kT, 256>>>(y, ln2_w, ln2_b, yn);
    gemm_nn_tf32<<<dim3(kMLP / 128, kT / 128), 256>>>(yn, ff1_w, ff1_b, nullptr,
                                                      hdn, kT, kMLP, kD, 1);
    gemm_nn_tf32<<<dim3(kD / 128, kT / 128), 256>>>(hdn, ff2_w, ff2_b, y, out,
                                                    kT, kD, kMLP, 0);
}

// round 6
// speedup vs baseline: 1.1570x; 1.1570x over previous
#include <cuda_runtime.h>
#include <math.h>
#include <stdint.h>

// ---------------- problem constants ----------------
namespace {
constexpr int kB  = 4;
constexpr int kN  = 1024;
constexpr int kD  = 768;
constexpr int kH  = 12;
constexpr int kHD = 64;
constexpr int kGP = 49;
constexpr int kMLP = 3072;
constexpr int kT  = kB * kN;     // 4096 tokens
constexpr int kBH = kB * kH;     // 48 batched heads
constexpr int kQD = 3 * kD;      // 2304
}

// ---------------- scratch (device globals: no allocation allowed) ----------------
__device__ float g_xn [kT * kD];
__device__ float g_qkv[kT * kQD];
__device__ float g_S  [(size_t)kBH * kN * kN];   // scores, later the mixed attn A
__device__ float g_G  [(size_t)kBH * kN * kN];   // gw @ gw^T
__device__ float g_gw [kBH * kN * 64];           // softmaxed group weights, padded 49->64
__device__ float g_inv[kBH * kN];                // 1/(colsum+eps)
__device__ float g_ctx[kT * kD];                 // merged-head attention output
__device__ float g_y  [kT * kD];                 // after proj residual
__device__ float g_yn [kT * kD];
__device__ float g_hdn[kT * kMLP];

__device__ __forceinline__ float gelu_exact(float x) {
    return 0.5f * x * (1.0f + erff(x * 0.70710678118654752440f));
}

__device__ __forceinline__ uint32_t f2tf32(float x) {
    uint32_t r;
    asm("cvt.rna.tf32.f32 %0, %1;" : "=r"(r) : "f"(x));
    return r;
}

// D += A(m16k8,row) * B(k8n8,col)   tf32
__device__ __forceinline__ void mma8(float* c, const uint32_t* a, const uint32_t* b) {
    asm volatile("mma.sync.aligned.m16n8k8.row.col.f32.tf32.tf32.f32 "
                 "{%0,%1,%2,%3}, {%4,%5,%6,%7}, {%8,%9}, {%0,%1,%2,%3};"
                 : "+f"(c[0]), "+f"(c[1]), "+f"(c[2]), "+f"(c[3])
                 : "r"(a[0]), "r"(a[1]), "r"(a[2]), "r"(a[3]),
                   "r"(b[0]), "r"(b[1]));
}

// ---------------- LayerNorm: one block (256 thr) per row of 768 ----------------
__global__ __launch_bounds__(256) void ln_kernel(const float* __restrict__ x,
                                                 const float* __restrict__ w,
                                                 const float* __restrict__ b,
                                                 float* __restrict__ out) {
    __shared__ float sh1[8], sh2[8];
    int row = blockIdx.x;
    int t = threadIdx.x;
    const float* xr = x + (size_t)row * kD;
    float v[3];
    float s = 0.f, s2 = 0.f;
#pragma unroll
    for (int i = 0; i < 3; i++) {
        v[i] = xr[t + i * 256];
        s  += v[i];
        s2 += v[i] * v[i];
    }
#pragma unroll
    for (int o = 16; o; o >>= 1) {
        s  += __shfl_xor_sync(0xffffffffu, s, o);
        s2 += __shfl_xor_sync(0xffffffffu, s2, o);
    }
    if ((t & 31) == 0) { sh1[t >> 5] = s; sh2[t >> 5] = s2; }
    __syncthreads();
    s = sh1[t & 7]; s2 = sh2[t & 7];
#pragma unroll
    for (int o = 4; o; o >>= 1) {
        s  += __shfl_xor_sync(0xffffffffu, s, o);
        s2 += __shfl_xor_sync(0xffffffffu, s2, o);
    }
    float mu   = s * (1.0f / kD);
    float var  = fmaxf(s2 * (1.0f / kD) - mu * mu, 0.f);
    float rstd = rsqrtf(var + 1e-5f);
    float* orow = out + (size_t)row * kD;
#pragma unroll
    for (int i = 0; i < 3; i++) {
        int c = t + i * 256;
        orow[c] = (v[i] - mu) * rstd * w[c] + b[c];
    }
}

// ------- TF32 dense GEMM (NN): C[M,N] = A[M,K] @ B[K,N] + bias (+gelu)(+res) --
// 128x128 block, 8 warps (4m x 2n), warp m32 x n64, K-step 16, reg-prefetch DB.
__global__ __launch_bounds__(256) void gemm_nn_tf32(
        const float* __restrict__ A, const float* __restrict__ B,
        const float* __restrict__ bias, const float* __restrict__ res,
        float* __restrict__ C, int M, int N, int K, int act) {
    __shared__ uint32_t As[128][20];   // [m][k]
    __shared__ uint32_t Bs[16][136];   // [k][n]
    int tid = threadIdx.x, lane = tid & 31, warp = tid >> 5;
    int g = lane >> 2, tg = lane & 3;
    int wm = (warp >> 1) * 32, wn = (warp & 1) * 64;
    int row0 = blockIdx.y * 128, col0 = blockIdx.x * 128;
    int ra = tid >> 2, ca = (tid & 3) * 4;       // A loader coords
    int kb = tid >> 5, nb = (tid & 31) * 4;      // B loader coords
    const float* Abase = A + (size_t)(row0 + ra) * K + ca;
    const float* Abase2 = A + (size_t)(row0 + ra + 64) * K + ca;
    const float* Bbase = B + (size_t)kb * N + col0 + nb;
    const float* Bbase2 = B + (size_t)(kb + 8) * N + col0 + nb;
    float acc[2][8][4] = {};
    float4 pa0 = *(const float4*)(Abase);
    float4 pa1 = *(const float4*)(Abase2);
    float4 pb0 = *(const float4*)(Bbase);
    float4 pb1 = *(const float4*)(Bbase2);
    for (int k0 = 0; k0 < K; k0 += 16) {
        As[ra][ca + 0] = f2tf32(pa0.x); As[ra][ca + 1] = f2tf32(pa0.y);
        As[ra][ca + 2] = f2tf32(pa0.z); As[ra][ca + 3] = f2tf32(pa0.w);
        As[ra + 64][ca + 0] = f2tf32(pa1.x); As[ra + 64][ca + 1] = f2tf32(pa1.y);
        As[ra + 64][ca + 2] = f2tf32(pa1.z); As[ra + 64][ca + 3] = f2tf32(pa1.w);
        Bs[kb][nb + 0] = f2tf32(pb0.x); Bs[kb][nb + 1] = f2tf32(pb0.y);
        Bs[kb][nb + 2] = f2tf32(pb0.z); Bs[kb][nb + 3] = f2tf32(pb0.w);
        Bs[kb + 8][nb + 0] = f2tf32(pb1.x); Bs[kb + 8][nb + 1] = f2tf32(pb1.y);
        Bs[kb + 8][nb + 2] = f2tf32(pb1.z); Bs[kb + 8][nb + 3] = f2tf32(pb1.w);
        __syncthreads();
        if (k0 + 16 < K) {     // prefetch next tiles: overlaps with mma below
            pa0 = *(const float4*)(Abase + k0 + 16);
            pa1 = *(const float4*)(Abase2 + k0 + 16);
            pb0 = *(const float4*)(Bbase + (size_t)(k0 + 16) * N);
            pb1 = *(const float4*)(Bbase2 + (size_t)(k0 + 16) * N);
        }
#pragma unroll
        for (int k8 = 0; k8 < 16; k8 += 8) {
            uint32_t af[2][4], bf[8][2];
#pragma unroll
            for (int mi = 0; mi < 2; mi++) {
                int r = wm + mi * 16 + g;
                af[mi][0] = As[r][k8 + tg];
                af[mi][1] = As[r + 8][k8 + tg];
                af[mi][2] = As[r][k8 + tg + 4];
                af[mi][3] = As[r + 8][k8 + tg + 4];
            }
#pragma unroll
            for (int nj = 0; nj < 8; nj++) {
                int n = wn + nj * 8 + g;
                bf[nj][0] = Bs[k8 + tg][n];
                bf[nj][1] = Bs[k8 + tg + 4][n];
            }
#pragma unroll
            for (int mi = 0; mi < 2; mi++)
#pragma unroll
                for (int nj = 0; nj < 8; nj++)
                    mma8(acc[mi][nj], af[mi], bf[nj]);
        }
        __syncthreads();
    }
#pragma unroll
    for (int mi = 0; mi < 2; mi++) {
#pragma unroll
        for (int nj = 0; nj < 8; nj++) {
            int r0 = row0 + wm + mi * 16 + g;
            int c = col0 + wn + nj * 8 + tg * 2;
            float b0 = bias[c], b1 = bias[c + 1];
            float o00 = acc[mi][nj][0] + b0, o01 = acc[mi][nj][1] + b1;
            float o10 = acc[mi][nj][2] + b0, o11 = acc[mi][nj][3] + b1;
            if (act) {
                o00 = gelu_exact(o00); o01 = gelu_exact(o01);
                o10 = gelu_exact(o10); o11 = gelu_exact(o11);
            }
            if (res) {
                o00 += res[(size_t)r0 * N + c];       o01 += res[(size_t)r0 * N + c + 1];
                o10 += res[(size_t)(r0 + 8) * N + c]; o11 += res[(size_t)(r0 + 8) * N + c + 1];
            }
            *(float2*)&C[(size_t)r0 * N + c]       = make_float2(o00, o01);
            *(float2*)&C[(size_t)(r0 + 8) * N + c] = make_float2(o10, o11);
        }
    }
}

// ---------------- scores S = scale * Q @ K^T (NT), tf32, batched over BH ------
__global__ __launch_bounds__(256) void score_tf32(const float* __restrict__ qkv,
                                                  float* __restrict__ S) {
    __shared__ uint32_t As[128][20];
    __shared__ uint32_t Bs[128][20];
    int bh = blockIdx.z, b = bh / kH, h = bh % kH;
    const float* qb = qkv + (size_t)b * kN * kQD + h * kHD;
    const float* kb = qb + kD;
    int tid = threadIdx.x, lane = tid & 31, warp = tid >> 5;
    int g = lane >> 2, tg = lane & 3;
    int wm = (warp >> 1) * 32, wn = (warp & 1) * 64;
    int n0 = blockIdx.y * 128, m0 = blockIdx.x * 128;
    float acc[2][8][4] = {};
    for (int k0 = 0; k0 < kHD; k0 += 16) {
#pragma unroll
        for (int i = 0; i < 2; i++) {
            int idx = tid + i * 256;
            int r = idx >> 2, c4 = (idx & 3) * 4;
            float4 qv = *(const float4*)(qb + (size_t)(n0 + r) * kQD + k0 + c4);
            float4 kv = *(const float4*)(kb + (size_t)(m0 + r) * kQD + k0 + c4);
            As[r][c4 + 0] = f2tf32(qv.x); As[r][c4 + 1] = f2tf32(qv.y);
            As[r][c4 + 2] = f2tf32(qv.z); As[r][c4 + 3] = f2tf32(qv.w);
            Bs[r][c4 + 0] = f2tf32(kv.x); Bs[r][c4 + 1] = f2tf32(kv.y);
            Bs[r][c4 + 2] = f2tf32(kv.z); Bs[r][c4 + 3] = f2tf32(kv.w);
        }
        __syncthreads();
#pragma unroll
        for (int k8 = 0; k8 < 16; k8 += 8) {
            uint32_t af[2][4], bf[8][2];
#pragma unroll
            for (int mi = 0; mi < 2; mi++) {
                int r = wm + mi * 16 + g;
                af[mi][0] = As[r][k8 + tg];
                af[mi][1] = As[r + 8][k8 + tg];
                af[mi][2] = As[r][k8 + tg + 4];
                af[mi][3] = As[r + 8][k8 + tg + 4];
            }
#pragma unroll
            for (int nj = 0; nj < 8; nj++) {
                int n = wn + nj * 8 + g;
                bf[nj][0] = Bs[n][k8 + tg];
                bf[nj][1] = Bs[n][k8 + tg + 4];
            }
#pragma unroll
            for (int mi = 0; mi < 2; mi++)
#pragma unroll
                for (int nj = 0; nj < 8; nj++)
                    mma8(acc[mi][nj], af[mi], bf[nj]);
        }
        __syncthreads();
    }
    float* Sb = S + (size_t)bh * kN * kN;
#pragma unroll
    for (int mi = 0; mi < 2; mi++) {
#pragma unroll
        for (int nj = 0; nj < 8; nj++) {
            int r0 = n0 + wm + mi * 16 + g;
            int c = m0 + wn + nj * 8 + tg * 2;
            *(float2*)&Sb[(size_t)r0 * kN + c] =
                make_float2(acc[mi][nj][0] * 0.125f, acc[mi][nj][1] * 0.125f);
            *(float2*)&Sb[(size_t)(r0 + 8) * kN + c] =
                make_float2(acc[mi][nj][2] * 0.125f, acc[mi][nj][3] * 0.125f);
        }
    }
}

// ---------------- G = gw @ gw^T (NT), tf32, K=64 padded ----------------
__global__ __launch_bounds__(256) void gmat_tf32(const float* __restrict__ gw,
                                                 float* __restrict__ G) {
    __shared__ uint32_t As[128][20];
    __shared__ uint32_t Bs[128][20];
    int bh = blockIdx.z;
    const float* gb = gw + (size_t)bh * kN * 64;
    int tid = threadIdx.x, lane = tid & 31, warp = tid >> 5;
    int g = lane >> 2, tg = lane & 3;
    int wm = (warp >> 1) * 32, wn = (warp & 1) * 64;
    int n0 = blockIdx.y * 128, m0 = blockIdx.x * 128;
    float acc[2][8][4] = {};
    for (int k0 = 0; k0 < 64; k0 += 16) {
#pragma unroll
        for (int i = 0; i < 2; i++) {
            int idx = tid + i * 256;
            int r = idx >> 2, c4 = (idx & 3) * 4;
            float4 av = *(const float4*)(gb + (size_t)(n0 + r) * 64 + k0 + c4);
            float4 bv = *(const float4*)(gb + (size_t)(m0 + r) * 64 + k0 + c4);
            As[r][c4 + 0] = f2tf32(av.x); As[r][c4 + 1] = f2tf32(av.y);
            As[r][c4 + 2] = f2tf32(av.z); As[r][c4 + 3] = f2tf32(av.w);
            Bs[r][c4 + 0] = f2tf32(bv.x); Bs[r][c4 + 1] = f2tf32(bv.y);
            Bs[r][c4 + 2] = f2tf32(bv.z); Bs[r][c4 + 3] = f2tf32(bv.w);
        }
        __syncthreads();
#pragma unroll
        for (int k8 = 0; k8 < 16; k8 += 8) {
            uint32_t af[2][4], bf[8][2];
#pragma unroll
            for (int mi = 0; mi < 2; mi++) {
                int r = wm + mi * 16 + g;
                af[mi][0] = As[r][k8 + tg];
                af[mi][1] = As[r + 8][k8 + tg];
                af[mi][2] = As[r][k8 + tg + 4];
                af[mi][3] = As[r + 8][k8 + tg + 4];
            }
#pragma unroll
            for (int nj = 0; nj < 8; nj++) {
                int n = wn + nj * 8 + g;
                bf[nj][0] = Bs[n][k8 + tg];
                bf[nj][1] = Bs[n][k8 + tg + 4];
            }
#pragma unroll
            for (int mi = 0; mi < 2; mi++)
#pragma unroll
                for (int nj = 0; nj < 8; nj++)
                    mma8(acc[mi][nj], af[mi], bf[nj]);
        }
        __syncthreads();
    }
    float* Gb = G + (size_t)bh * kN * kN;
#pragma unroll
    for (int mi = 0; mi < 2; mi++) {
#pragma unroll
        for (int nj = 0; nj < 8; nj++) {
            int r0 = n0 + wm + mi * 16 + g;
            int c = m0 + wn + nj * 8 + tg * 2;
            *(float2*)&Gb[(size_t)r0 * kN + c] =
                make_float2(acc[mi][nj][0], acc[mi][nj][1]);
            *(float2*)&Gb[(size_t)(r0 + 8) * kN + c] =
                make_float2(acc[mi][nj][2], acc[mi][nj][3]);
        }
    }
}

// ------- out = (A * inv[k]) @ V  (NN), tf32; heads merged into ctx ------------
__global__ __launch_bounds__(256) void av_tf32(const float* __restrict__ Sa,
                                               const float* __restrict__ inv,
                                               const float* __restrict__ qkv,
                                               float* __restrict__ ctx) {
    __shared__ uint32_t As[128][20];
    __shared__ uint32_t Bs[16][72];
    int bh = blockIdx.z, b = bh / kH, h = bh % kH;
    const float* Ab = Sa + (size_t)bh * kN * kN;
    const float* vb = qkv + (size_t)b * kN * kQD + 2 * kD + h * kHD;
    const float* invb = inv + bh * kN;
    int tid = threadIdx.x, lane = tid & 31, warp = tid >> 5;
    int g = lane >> 2, tg = lane & 3;
    int wm = (warp >> 1) * 32, wn = (warp & 1) * 32;
    int row0 = blockIdx.y * 128;
    float acc[2][4][4] = {};
    for (int k0 = 0; k0 < kN; k0 += 16) {
#pragma unroll
        for (int i = 0; i < 2; i++) {
            int idx = tid + i * 256;
            int r = idx >> 2, c4 = (idx & 3) * 4;
            float4 v = *(const float4*)(Ab + (size_t)(row0 + r) * kN + k0 + c4);
            As[r][c4 + 0] = f2tf32(v.x); As[r][c4 + 1] = f2tf32(v.y);
            As[r][c4 + 2] = f2tf32(v.z); As[r][c4 + 3] = f2tf32(v.w);
        }
        {
            int kr = tid >> 4, nc = (tid & 15) * 4;
            float iv = invb[k0 + kr];
            float4 v = *(const float4*)(vb + (size_t)(k0 + kr) * kQD + nc);
            Bs[kr][nc + 0] = f2tf32(v.x * iv); Bs[kr][nc + 1] = f2tf32(v.y * iv);
            Bs[kr][nc + 2] = f2tf32(v.z * iv); Bs[kr][nc + 3] = f2tf32(v.w * iv);
        }
        __syncthreads();
#pragma unroll
        for (int k8 = 0; k8 < 16; k8 += 8) {
            uint32_t af[2][4], bf[4][2];
#pragma unroll
            for (int mi = 0; mi < 2; mi++) {
                int r = wm + mi * 16 + g;
                af[mi][0] = As[r][k8 + tg];
                af[mi][1] = As[r + 8][k8 + tg];
                af[mi][2] = As[r][k8 + tg + 4];
                af[mi][3] = As[r + 8][k8 + tg + 4];
            }
#pragma unroll
            for (int nj = 0; nj < 4; nj++) {
                int n = wn + nj * 8 + g;
                bf[nj][0] = Bs[k8 + tg][n];
                bf[nj][1] = Bs[k8 + tg + 4][n];
            }
#pragma unroll
            for (int mi = 0; mi < 2; mi++)
#pragma unroll
                for (int nj = 0; nj < 4; nj++)
                    mma8(acc[mi][nj], af[mi], bf[nj]);
        }
        __syncthreads();
    }
#pragma unroll
    for (int mi = 0; mi < 2; mi++) {
#pragma unroll
        for (int nj = 0; nj < 4; nj++) {
            int tok0 = b * kN + row0 + wm + mi * 16 + g;
            int c = h * kHD + wn + nj * 8 + tg * 2;
            *(float2*)&ctx[(size_t)tok0 * kD + c] =
                make_float2(acc[mi][nj][0], acc[mi][nj][1]);
            *(float2*)&ctx[(size_t)(tok0 + 8) * kD + c] =
                make_float2(acc[mi][nj][2], acc[mi][nj][3]);
        }
    }
}

// ---- group weights: gw = softmax(gelu(V @ gp^T)) padded to 64 ----
__global__ __launch_bounds__(256) void gw_kernel(const float* __restrict__ qkv,
                                                 const float* __restrict__ gp_w,
                                                 float* __restrict__ gw) {
    __shared__ __align__(16) float gps[kGP][68];
    __shared__ __align__(16) float Vs[64][68];
    int bh = blockIdx.y;
    int b = bh / kH, h = bh % kH;
    int n0 = blockIdx.x * 64;
    int tid = threadIdx.x;
    const float* gph = gp_w + (size_t)h * kGP * kHD;
    for (int i = tid; i < kGP * 16; i += 256) {
        int r = i >> 4, c4 = (i & 15) * 4;
        *(float4*)&gps[r][c4] = *(const float4*)(gph + r * kHD + c4);
    }
    const float* vb = qkv + (size_t)(b * kN + n0) * kQD + 2 * kD + h * kHD;
    for (int i = tid; i < 64 * 16; i += 256) {
        int r = i >> 4, c4 = (i & 15) * 4;
        *(float4*)&Vs[r][c4] = *(const float4*)(vb + (size_t)r * kQD + c4);
    }
    __syncthreads();
    int r = tid >> 2;
    int c0 = tid & 3;
    float val[13];
    float mx = -1e30f;
#pragma unroll
    for (int j = 0; j < 13; j++) {
        int c = c0 + 4 * j;
        float acc = 0.f;
        if (c < kGP) {
#pragma unroll
            for (int d = 0; d < kHD; d += 4) {
                float4 vv = *(const float4*)&Vs[r][d];
                float4 gg = *(const float4*)&gps[c][d];
                acc += vv.x * gg.x + vv.y * gg.y + vv.z * gg.z + vv.w * gg.w;
            }
            acc = gelu_exact(acc);
            mx = fmaxf(mx, acc);
        }
        val[j] = acc;
    }
    mx = fmaxf(mx, __shfl_xor_sync(0xffffffffu, mx, 1));
    mx = fmaxf(mx, __shfl_xor_sync(0xffffffffu, mx, 2));
    float sum = 0.f;
#pragma unroll
    for (int j = 0; j < 13; j++) {
        int c = c0 + 4 * j;
        val[j] = (c < kGP) ? __expf(val[j] - mx) : 0.f;
        sum += val[j];
    }
    sum += __shfl_xor_sync(0xffffffffu, sum, 1);
    sum += __shfl_xor_sync(0xffffffffu, sum, 2);
    float is = 1.f / sum;
    float* grow = gw + (size_t)(bh * kN + n0 + r) * 64;
#pragma unroll
    for (int j = 0; j < 16; j++) {
        int c = c0 + 4 * j;
        if (c < 64) grow[c] = (j < 13 && c < kGP) ? val[j] * is : 0.f;
    }
}

// ------- per-row: P = softmax(S*G); A = (1-a)P + a*G  (A overwrites S) -------
__global__ __launch_bounds__(256) void rowmix_kernel(const float* __restrict__ alpha,
                                                     float* __restrict__ S,
                                                     const float* __restrict__ G) {
    __shared__ float sh1[8];
    int gr = blockIdx.x;                 // bh*N + n
    int h = (gr >> 10) % kH;
    size_t off = (size_t)gr * kN;
    int t = threadIdx.x;
    float a = 1.f / (1.f + __expf(-alpha[h]));
    float gv[4], tv[4];
    float mx = -1e30f;
#pragma unroll
    for (int i = 0; i < 4; i++) {
        int m = t + i * 256;
        float sv = S[off + m];
        gv[i] = G[off + m];
        tv[i] = sv * gv[i];
        mx = fmaxf(mx, tv[i]);
    }
    for (int o = 16; o; o >>= 1) mx = fmaxf(mx, __shfl_xor_sync(0xffffffffu, mx, o));
    if ((t & 31) == 0) sh1[t >> 5] = mx;
    __syncthreads();
    mx = sh1[t & 7];
    for (int o = 4; o; o >>= 1) mx = fmaxf(mx, __shfl_xor_sync(0xffffffffu, mx, o));
    __syncthreads();
    float e[4], sum = 0.f;
#pragma unroll
    for (int i = 0; i < 4; i++) { e[i] = __expf(tv[i] - mx); sum += e[i]; }
    for (int o = 16; o; o >>= 1) sum += __shfl_xor_sync(0xffffffffu, sum, o);
    if ((t & 31) == 0) sh1[t >> 5] = sum;
    __syncthreads();
    sum = sh1[t & 7];
    for (int o = 4; o; o >>= 1) sum += __shfl_xor_sync(0xffffffffu, sum, o);
    float isum = 1.f / sum;
#pragma unroll
    for (int i = 0; i < 4; i++) {
        int m = t + i * 256;
        S[off + m] = (1.f - a) * e[i] * isum + a * gv[i];
    }
}

// ------- column sums over n (axis=2), stores 1/(sum+1e-8) -------
__global__ __launch_bounds__(256) void colsum_kernel(const float* __restrict__ Sa,
                                                     float* __restrict__ inv) {
    int idx = blockIdx.x * 256 + threadIdx.x;   // bh*N + m
    int bh = idx >> 10, m = idx & 1023;
    const float* p = Sa + (size_t)bh * kN * kN + m;
    float s = 0.f;
#pragma unroll 4
    for (int n = 0; n < kN; n++) s += p[(size_t)n * kN];
    inv[idx] = 1.f / (s + 1e-8f);
}

// ---------------- launch ----------------
extern "C" void kernel_launch(void* const* d_in, const int* in_sizes, int n_in,
                              void* d_out, int out_size) {
    const float* x      = (const float*)d_in[0];
    const float* ln1_w  = (const float*)d_in[1];
    const float* ln1_b  = (const float*)d_in[2];
    const float* qkv_w  = (const float*)d_in[3];
    const float* qkv_b  = (const float*)d_in[4];
    const float* proj_w = (const float*)d_in[5];
    const float* proj_b = (const float*)d_in[6];
    const float* gp_w   = (const float*)d_in[7];
    const float* alpha  = (const float*)d_in[8];
    const float* ln2_w  = (const float*)d_in[9];
    const float* ln2_b  = (const float*)d_in[10];
    const float* ff1_w  = (const float*)d_in[11];
    const float* ff1_b  = (const float*)d_in[12];
    const float* ff2_w  = (const float*)d_in[13];
    const float* ff2_b  = (const float*)d_in[14];
    float* out = (float*)d_out;

    float *xn, *qkv, *S, *G, *gw, *inv, *ctx, *y, *yn, *hdn;
    cudaGetSymbolAddress((void**)&xn,  g_xn);
    cudaGetSymbolAddress((void**)&qkv, g_qkv);
    cudaGetSymbolAddress((void**)&S,   g_S);
    cudaGetSymbolAddress((void**)&G,   g_G);
    cudaGetSymbolAddress((void**)&gw,  g_gw);
    cudaGetSymbolAddress((void**)&inv, g_inv);
    cudaGetSymbolAddress((void**)&ctx, g_ctx);
    cudaGetSymbolAddress((void**)&y,   g_y);
    cudaGetSymbolAddress((void**)&yn,  g_yn);
    cudaGetSymbolAddress((void**)&hdn, g_hdn);

    // attention branch
    ln_kernel<<<kT, 256>>>(x, ln1_w, ln1_b, xn);
    gemm_nn_tf32<<<dim3(kQD / 128, kT / 128), 256>>>(xn, qkv_w, qkv_b, nullptr,
                                                     qkv, kT, kQD, kD, 0);
    score_tf32<<<dim3(8, 8, kBH), 256>>>(qkv, S);
    gw_kernel<<<dim3(kN / 64, kBH), 256>>>(qkv, gp_w, gw);
    gmat_tf32<<<dim3(8, 8, kBH), 256>>>(gw, G);
    rowmix_kernel<<<kBH * kN, 256>>>(alpha, S, G);
    colsum_kernel<<<kBH * kN / 256, 256>>>(S, inv);
    av_tf32<<<dim3(1, 8, kBH), 256>>>(S, inv, qkv, ctx);
    gemm_nn_tf32<<<dim3(kD / 128, kT / 128), 256>>>(ctx, proj_w, proj_b, x, y,
                                                    kT, kD, kD, 0);
    // FFN branch
    ln_kernel<<<kT, 256>>>(y, ln2_w, ln2_b, yn);
    gemm_nn_tf32<<<dim3(kMLP / 128, kT / 128), 256>>>(yn, ff1_w, ff1_b, nullptr,
                                                      hdn, kT, kMLP, kD, 1);
    gemm_nn_tf32<<<dim3(kD / 128, kT / 128), 256>>>(hdn, ff2_w, ff2_b, y, out,
                                                    kT, kD, kMLP, 0);
}

// round 7
// speedup vs baseline: 1.3004x; 1.1239x over previous
#include <cuda_runtime.h>
#include <math.h>
#include <stdint.h>

// ---------------- problem constants ----------------
namespace {
constexpr int kB  = 4;
constexpr int kN  = 1024;
constexpr int kD  = 768;
constexpr int kH  = 12;
constexpr int kHD = 64;
constexpr int kGP = 49;
constexpr int kMLP = 3072;
constexpr int kT  = kB * kN;     // 4096 tokens
constexpr int kBH = kB * kH;     // 48 batched heads
constexpr int kQD = 3 * kD;      // 2304
}

// ---------------- scratch (device globals: no allocation allowed) ----------------
__device__ float g_xn [kT * kD];
__device__ float g_qkv[kT * kQD];
__device__ float g_S  [(size_t)kBH * kN * kN];   // scores, later the mixed attn A
__device__ float g_G  [(size_t)kBH * kN * kN];   // gw @ gw^T
__device__ float g_gw [kBH * kN * 64];           // softmaxed group weights, padded 49->64
__device__ float g_inv[kBH * kN];                // 1/(colsum+eps)
__device__ float g_ctx[kT * kD];                 // merged-head attention output
__device__ float g_y  [kT * kD];                 // after proj residual
__device__ float g_yn [kT * kD];
__device__ float g_hdn[kT * kMLP];

__device__ __forceinline__ float gelu_exact(float x) {
    return 0.5f * x * (1.0f + erff(x * 0.70710678118654752440f));
}

__device__ __forceinline__ uint32_t f2tf32(float x) {
    uint32_t r;
    asm("cvt.rna.tf32.f32 %0, %1;" : "=r"(r) : "f"(x));
    return r;
}

// D += A(m16k8,row) * B(k8n8,col)   tf32
__device__ __forceinline__ void mma8(float* c, const uint32_t* a, const uint32_t* b) {
    asm volatile("mma.sync.aligned.m16n8k8.row.col.f32.tf32.tf32.f32 "
                 "{%0,%1,%2,%3}, {%4,%5,%6,%7}, {%8,%9}, {%0,%1,%2,%3};"
                 : "+f"(c[0]), "+f"(c[1]), "+f"(c[2]), "+f"(c[3])
                 : "r"(a[0]), "r"(a[1]), "r"(a[2]), "r"(a[3]),
                   "r"(b[0]), "r"(b[1]));
}

// ---------------- LayerNorm: one block (256 thr) per row of 768 ----------------
__global__ __launch_bounds__(256) void ln_kernel(const float* __restrict__ x,
                                                 const float* __restrict__ w,
                                                 const float* __restrict__ b,
                                                 float* __restrict__ out) {
    __shared__ float sh1[8], sh2[8];
    int row = blockIdx.x;
    int t = threadIdx.x;
    const float* xr = x + (size_t)row * kD;
    float v[3];
    float s = 0.f, s2 = 0.f;
#pragma unroll
    for (int i = 0; i < 3; i++) {
        v[i] = xr[t + i * 256];
        s  += v[i];
        s2 += v[i] * v[i];
    }
#pragma unroll
    for (int o = 16; o; o >>= 1) {
        s  += __shfl_xor_sync(0xffffffffu, s, o);
        s2 += __shfl_xor_sync(0xffffffffu, s2, o);
    }
    if ((t & 31) == 0) { sh1[t >> 5] = s; sh2[t >> 5] = s2; }
    __syncthreads();
    s = sh1[t & 7]; s2 = sh2[t & 7];
#pragma unroll
    for (int o = 4; o; o >>= 1) {
        s  += __shfl_xor_sync(0xffffffffu, s, o);
        s2 += __shfl_xor_sync(0xffffffffu, s2, o);
    }
    float mu   = s * (1.0f / kD);
    float var  = fmaxf(s2 * (1.0f / kD) - mu * mu, 0.f);
    float rstd = rsqrtf(var + 1e-5f);
    float* orow = out + (size_t)row * kD;
#pragma unroll
    for (int i = 0; i < 3; i++) {
        int c = t + i * 256;
        orow[c] = (v[i] - mu) * rstd * w[c] + b[c];
    }
}

// ------- TF32 dense GEMM (NN): C[M,N] = A[M,K] @ B[K,N] + bias (+gelu)(+res) --
// 128x128 block, 8 warps (4m x 2n), warp m32 x n64, K-step 16, reg-prefetch DB.
__global__ __launch_bounds__(256) void gemm_nn_tf32(
        const float* __restrict__ A, const float* __restrict__ B,
        const float* __restrict__ bias, const float* __restrict__ res,
        float* __restrict__ C, int M, int N, int K, int act) {
    __shared__ uint32_t As[128][20];   // [m][k]
    __shared__ uint32_t Bs[16][136];   // [k][n]
    int tid = threadIdx.x, lane = tid & 31, warp = tid >> 5;
    int g = lane >> 2, tg = lane & 3;
    int wm = (warp >> 1) * 32, wn = (warp & 1) * 64;
    int row0 = blockIdx.y * 128, col0 = blockIdx.x * 128;
    int ra = tid >> 2, ca = (tid & 3) * 4;       // A loader coords
    int kb = tid >> 5, nb = (tid & 31) * 4;      // B loader coords
    const float* Abase = A + (size_t)(row0 + ra) * K + ca;
    const float* Abase2 = A + (size_t)(row0 + ra + 64) * K + ca;
    const float* Bbase = B + (size_t)kb * N + col0 + nb;
    const float* Bbase2 = B + (size_t)(kb + 8) * N + col0 + nb;
    float acc[2][8][4] = {};
    float4 pa0 = *(const float4*)(Abase);
    float4 pa1 = *(const float4*)(Abase2);
    float4 pb0 = *(const float4*)(Bbase);
    float4 pb1 = *(const float4*)(Bbase2);
    for (int k0 = 0; k0 < K; k0 += 16) {
        As[ra][ca + 0] = f2tf32(pa0.x); As[ra][ca + 1] = f2tf32(pa0.y);
        As[ra][ca + 2] = f2tf32(pa0.z); As[ra][ca + 3] = f2tf32(pa0.w);
        As[ra + 64][ca + 0] = f2tf32(pa1.x); As[ra + 64][ca + 1] = f2tf32(pa1.y);
        As[ra + 64][ca + 2] = f2tf32(pa1.z); As[ra + 64][ca + 3] = f2tf32(pa1.w);
        Bs[kb][nb + 0] = f2tf32(pb0.x); Bs[kb][nb + 1] = f2tf32(pb0.y);
        Bs[kb][nb + 2] = f2tf32(pb0.z); Bs[kb][nb + 3] = f2tf32(pb0.w);
        Bs[kb + 8][nb + 0] = f2tf32(pb1.x); Bs[kb + 8][nb + 1] = f2tf32(pb1.y);
        Bs[kb + 8][nb + 2] = f2tf32(pb1.z); Bs[kb + 8][nb + 3] = f2tf32(pb1.w);
        __syncthreads();
        if (k0 + 16 < K) {     // prefetch next tiles: overlaps with mma below
            pa0 = *(const float4*)(Abase + k0 + 16);
            pa1 = *(const float4*)(Abase2 + k0 + 16);
            pb0 = *(const float4*)(Bbase + (size_t)(k0 + 16) * N);
            pb1 = *(const float4*)(Bbase2 + (size_t)(k0 + 16) * N);
        }
#pragma unroll
        for (int k8 = 0; k8 < 16; k8 += 8) {
            uint32_t af[2][4], bf[8][2];
#pragma unroll
            for (int mi = 0; mi < 2; mi++) {
                int r = wm + mi * 16 + g;
                af[mi][0] = As[r][k8 + tg];
                af[mi][1] = As[r + 8][k8 + tg];
                af[mi][2] = As[r][k8 + tg + 4];
                af[mi][3] = As[r + 8][k8 + tg + 4];
            }
#pragma unroll
            for (int nj = 0; nj < 8; nj++) {
                int n = wn + nj * 8 + g;
                bf[nj][0] = Bs[k8 + tg][n];
                bf[nj][1] = Bs[k8 + tg + 4][n];
            }
#pragma unroll
            for (int mi = 0; mi < 2; mi++)
#pragma unroll
                for (int nj = 0; nj < 8; nj++)
                    mma8(acc[mi][nj], af[mi], bf[nj]);
        }
        __syncthreads();
    }
#pragma unroll
    for (int mi = 0; mi < 2; mi++) {
#pragma unroll
        for (int nj = 0; nj < 8; nj++) {
            int r0 = row0 + wm + mi * 16 + g;
            int c = col0 + wn + nj * 8 + tg * 2;
            float b0 = bias[c], b1 = bias[c + 1];
            float o00 = acc[mi][nj][0] + b0, o01 = acc[mi][nj][1] + b1;
            float o10 = acc[mi][nj][2] + b0, o11 = acc[mi][nj][3] + b1;
            if (act) {
                o00 = gelu_exact(o00); o01 = gelu_exact(o01);
                o10 = gelu_exact(o10); o11 = gelu_exact(o11);
            }
            if (res) {
                o00 += res[(size_t)r0 * N + c];       o01 += res[(size_t)r0 * N + c + 1];
                o10 += res[(size_t)(r0 + 8) * N + c]; o11 += res[(size_t)(r0 + 8) * N + c + 1];
            }
            *(float2*)&C[(size_t)r0 * N + c]       = make_float2(o00, o01);
            *(float2*)&C[(size_t)(r0 + 8) * N + c] = make_float2(o10, o11);
        }
    }
}

// ---------------- scores S = scale * Q @ K^T (NT), tf32, batched over BH ------
__global__ __launch_bounds__(256) void score_tf32(const float* __restrict__ qkv,
                                                  float* __restrict__ S) {
    __shared__ uint32_t As[128][20];
    __shared__ uint32_t Bs[128][20];
    int bh = blockIdx.z, b = bh / kH, h = bh % kH;
    const float* qb = qkv + (size_t)b * kN * kQD + h * kHD;
    const float* kb = qb + kD;
    int tid = threadIdx.x, lane = tid & 31, warp = tid >> 5;
    int g = lane >> 2, tg = lane & 3;
    int wm = (warp >> 1) * 32, wn = (warp & 1) * 64;
    int n0 = blockIdx.y * 128, m0 = blockIdx.x * 128;
    int ra = tid >> 2, ca = (tid & 3) * 4;
    const float* Qp0 = qb + (size_t)(n0 + ra) * kQD + ca;
    const float* Qp1 = Qp0 + (size_t)64 * kQD;
    const float* Kp0 = kb + (size_t)(m0 + ra) * kQD + ca;
    const float* Kp1 = Kp0 + (size_t)64 * kQD;
    float acc[2][8][4] = {};
    float4 q0 = *(const float4*)Qp0, q1 = *(const float4*)Qp1;
    float4 v0 = *(const float4*)Kp0, v1 = *(const float4*)Kp1;
    for (int k0 = 0; k0 < kHD; k0 += 16) {
        As[ra][ca + 0] = f2tf32(q0.x); As[ra][ca + 1] = f2tf32(q0.y);
        As[ra][ca + 2] = f2tf32(q0.z); As[ra][ca + 3] = f2tf32(q0.w);
        As[ra + 64][ca + 0] = f2tf32(q1.x); As[ra + 64][ca + 1] = f2tf32(q1.y);
        As[ra + 64][ca + 2] = f2tf32(q1.z); As[ra + 64][ca + 3] = f2tf32(q1.w);
        Bs[ra][ca + 0] = f2tf32(v0.x); Bs[ra][ca + 1] = f2tf32(v0.y);
        Bs[ra][ca + 2] = f2tf32(v0.z); Bs[ra][ca + 3] = f2tf32(v0.w);
        Bs[ra + 64][ca + 0] = f2tf32(v1.x); Bs[ra + 64][ca + 1] = f2tf32(v1.y);
        Bs[ra + 64][ca + 2] = f2tf32(v1.z); Bs[ra + 64][ca + 3] = f2tf32(v1.w);
        __syncthreads();
        if (k0 + 16 < kHD) {
            q0 = *(const float4*)(Qp0 + k0 + 16);
            q1 = *(const float4*)(Qp1 + k0 + 16);
            v0 = *(const float4*)(Kp0 + k0 + 16);
            v1 = *(const float4*)(Kp1 + k0 + 16);
        }
#pragma unroll
        for (int k8 = 0; k8 < 16; k8 += 8) {
            uint32_t af[2][4], bf[8][2];
#pragma unroll
            for (int mi = 0; mi < 2; mi++) {
                int r = wm + mi * 16 + g;
                af[mi][0] = As[r][k8 + tg];
                af[mi][1] = As[r + 8][k8 + tg];
                af[mi][2] = As[r][k8 + tg + 4];
                af[mi][3] = As[r + 8][k8 + tg + 4];
            }
#pragma unroll
            for (int nj = 0; nj < 8; nj++) {
                int n = wn + nj * 8 + g;
                bf[nj][0] = Bs[n][k8 + tg];
                bf[nj][1] = Bs[n][k8 + tg + 4];
            }
#pragma unroll
            for (int mi = 0; mi < 2; mi++)
#pragma unroll
                for (int nj = 0; nj < 8; nj++)
                    mma8(acc[mi][nj], af[mi], bf[nj]);
        }
        __syncthreads();
    }
    float* Sb = S + (size_t)bh * kN * kN;
#pragma unroll
    for (int mi = 0; mi < 2; mi++) {
#pragma unroll
        for (int nj = 0; nj < 8; nj++) {
            int r0 = n0 + wm + mi * 16 + g;
            int c = m0 + wn + nj * 8 + tg * 2;
            *(float2*)&Sb[(size_t)r0 * kN + c] =
                make_float2(acc[mi][nj][0] * 0.125f, acc[mi][nj][1] * 0.125f);
            *(float2*)&Sb[(size_t)(r0 + 8) * kN + c] =
                make_float2(acc[mi][nj][2] * 0.125f, acc[mi][nj][3] * 0.125f);
        }
    }
}

// ---------------- G = gw @ gw^T (NT), tf32, K=64 padded ----------------
__global__ __launch_bounds__(256) void gmat_tf32(const float* __restrict__ gw,
                                                 float* __restrict__ G) {
    __shared__ uint32_t As[128][20];
    __shared__ uint32_t Bs[128][20];
    int bh = blockIdx.z;
    const float* gb = gw + (size_t)bh * kN * 64;
    int tid = threadIdx.x, lane = tid & 31, warp = tid >> 5;
    int g = lane >> 2, tg = lane & 3;
    int wm = (warp >> 1) * 32, wn = (warp & 1) * 64;
    int n0 = blockIdx.y * 128, m0 = blockIdx.x * 128;
    int ra = tid >> 2, ca = (tid & 3) * 4;
    const float* Ap0 = gb + (size_t)(n0 + ra) * 64 + ca;
    const float* Ap1 = Ap0 + (size_t)64 * 64;
    const float* Bp0 = gb + (size_t)(m0 + ra) * 64 + ca;
    const float* Bp1 = Bp0 + (size_t)64 * 64;
    float acc[2][8][4] = {};
    float4 a0 = *(const float4*)Ap0, a1 = *(const float4*)Ap1;
    float4 b0 = *(const float4*)Bp0, b1 = *(const float4*)Bp1;
    for (int k0 = 0; k0 < 64; k0 += 16) {
        As[ra][ca + 0] = f2tf32(a0.x); As[ra][ca + 1] = f2tf32(a0.y);
        As[ra][ca + 2] = f2tf32(a0.z); As[ra][ca + 3] = f2tf32(a0.w);
        As[ra + 64][ca + 0] = f2tf32(a1.x); As[ra + 64][ca + 1] = f2tf32(a1.y);
        As[ra + 64][ca + 2] = f2tf32(a1.z); As[ra + 64][ca + 3] = f2tf32(a1.w);
        Bs[ra][ca + 0] = f2tf32(b0.x); Bs[ra][ca + 1] = f2tf32(b0.y);
        Bs[ra][ca + 2] = f2tf32(b0.z); Bs[ra][ca + 3] = f2tf32(b0.w);
        Bs[ra + 64][ca + 0] = f2tf32(b1.x); Bs[ra + 64][ca + 1] = f2tf32(b1.y);
        Bs[ra + 64][ca + 2] = f2tf32(b1.z); Bs[ra + 64][ca + 3] = f2tf32(b1.w);
        __syncthreads();
        if (k0 + 16 < 64) {
            a0 = *(const float4*)(Ap0 + k0 + 16);
            a1 = *(const float4*)(Ap1 + k0 + 16);
            b0 = *(const float4*)(Bp0 + k0 + 16);
            b1 = *(const float4*)(Bp1 + k0 + 16);
        }
#pragma unroll
        for (int k8 = 0; k8 < 16; k8 += 8) {
            uint32_t af[2][4], bf[8][2];
#pragma unroll
            for (int mi = 0; mi < 2; mi++) {
                int r = wm + mi * 16 + g;
                af[mi][0] = As[r][k8 + tg];
                af[mi][1] = As[r + 8][k8 + tg];
                af[mi][2] = As[r][k8 + tg + 4];
                af[mi][3] = As[r + 8][k8 + tg + 4];
            }
#pragma unroll
            for (int nj = 0; nj < 8; nj++) {
                int n = wn + nj * 8 + g;
                bf[nj][0] = Bs[n][k8 + tg];
                bf[nj][1] = Bs[n][k8 + tg + 4];
            }
#pragma unroll
            for (int mi = 0; mi < 2; mi++)
#pragma unroll
                for (int nj = 0; nj < 8; nj++)
                    mma8(acc[mi][nj], af[mi], bf[nj]);
        }
        __syncthreads();
    }
    float* Gb = G + (size_t)bh * kN * kN;
#pragma unroll
    for (int mi = 0; mi < 2; mi++) {
#pragma unroll
        for (int nj = 0; nj < 8; nj++) {
            int r0 = n0 + wm + mi * 16 + g;
            int c = m0 + wn + nj * 8 + tg * 2;
            *(float2*)&Gb[(size_t)r0 * kN + c] =
                make_float2(acc[mi][nj][0], acc[mi][nj][1]);
            *(float2*)&Gb[(size_t)(r0 + 8) * kN + c] =
                make_float2(acc[mi][nj][2], acc[mi][nj][3]);
        }
    }
}

// ------- out = (A * inv[k]) @ V  (NN), tf32; heads merged into ctx ------------
__global__ __launch_bounds__(256) void av_tf32(const float* __restrict__ Sa,
                                               const float* __restrict__ inv,
                                               const float* __restrict__ qkv,
                                               float* __restrict__ ctx) {
    __shared__ uint32_t As[128][20];
    __shared__ uint32_t Bs[16][72];
    int bh = blockIdx.z, b = bh / kH, h = bh % kH;
    const float* Ab = Sa + (size_t)bh * kN * kN;
    const float* vb = qkv + (size_t)b * kN * kQD + 2 * kD + h * kHD;
    const float* invb = inv + bh * kN;
    int tid = threadIdx.x, lane = tid & 31, warp = tid >> 5;
    int g = lane >> 2, tg = lane & 3;
    int wm = (warp >> 1) * 32, wn = (warp & 1) * 32;
    int row0 = blockIdx.y * 128;
    int ra = tid >> 2, ca = (tid & 3) * 4;
    int kr = tid >> 4, nc = (tid & 15) * 4;
    const float* Ap0 = Ab + (size_t)(row0 + ra) * kN + ca;
    const float* Ap1 = Ap0 + (size_t)64 * kN;
    const float* Vp = vb + (size_t)kr * kQD + nc;
    float acc[2][4][4] = {};
    float4 a0 = *(const float4*)Ap0;
    float4 a1 = *(const float4*)Ap1;
    float4 vv = *(const float4*)Vp;
    float iv = invb[kr];
    for (int k0 = 0; k0 < kN; k0 += 16) {
        As[ra][ca + 0] = f2tf32(a0.x); As[ra][ca + 1] = f2tf32(a0.y);
        As[ra][ca + 2] = f2tf32(a0.z); As[ra][ca + 3] = f2tf32(a0.w);
        As[ra + 64][ca + 0] = f2tf32(a1.x); As[ra + 64][ca + 1] = f2tf32(a1.y);
        As[ra + 64][ca + 2] = f2tf32(a1.z); As[ra + 64][ca + 3] = f2tf32(a1.w);
        Bs[kr][nc + 0] = f2tf32(vv.x * iv); Bs[kr][nc + 1] = f2tf32(vv.y * iv);
        Bs[kr][nc + 2] = f2tf32(vv.z * iv); Bs[kr][nc + 3] = f2tf32(vv.w * iv);
        __syncthreads();
        if (k0 + 16 < kN) {
            a0 = *(const float4*)(Ap0 + k0 + 16);
            a1 = *(const float4*)(Ap1 + k0 + 16);
            vv = *(const float4*)(Vp + (size_t)(k0 + 16) * kQD);
            iv = invb[k0 + 16 + kr];
        }
#pragma unroll
        for (int k8 = 0; k8 < 16; k8 += 8) {
            uint32_t af[2][4], bf[4][2];
#pragma unroll
            for (int mi = 0; mi < 2; mi++) {
                int r = wm + mi * 16 + g;
                af[mi][0] = As[r][k8 + tg];
                af[mi][1] = As[r + 8][k8 + tg];
                af[mi][2] = As[r][k8 + tg + 4];
                af[mi][3] = As[r + 8][k8 + tg + 4];
            }
#pragma unroll
            for (int nj = 0; nj < 4; nj++) {
                int n = wn + nj * 8 + g;
                bf[nj][0] = Bs[k8 + tg][n];
                bf[nj][1] = Bs[k8 + tg + 4][n];
            }
#pragma unroll
            for (int mi = 0; mi < 2; mi++)
#pragma unroll
                for (int nj = 0; nj < 4; nj++)
                    mma8(acc[mi][nj], af[mi], bf[nj]);
        }
        __syncthreads();
    }
#pragma unroll
    for (int mi = 0; mi < 2; mi++) {
#pragma unroll
        for (int nj = 0; nj < 4; nj++) {
            int tok0 = b * kN + row0 + wm + mi * 16 + g;
            int c = h * kHD + wn + nj * 8 + tg * 2;
            *(float2*)&ctx[(size_t)tok0 * kD + c] =
                make_float2(acc[mi][nj][0], acc[mi][nj][1]);
            *(float2*)&ctx[(size_t)(tok0 + 8) * kD + c] =
                make_float2(acc[mi][nj][2], acc[mi][nj][3]);
        }
    }
}

// ---- group weights: gw = softmax(gelu(V @ gp^T)) padded to 64 ----
__global__ __launch_bounds__(256) void gw_kernel(const float* __restrict__ qkv,
                                                 const float* __restrict__ gp_w,
                                                 float* __restrict__ gw) {
    __shared__ __align__(16) float gps[kGP][68];
    __shared__ __align__(16) float Vs[64][68];
    int bh = blockIdx.y;
    int b = bh / kH, h = bh % kH;
    int n0 = blockIdx.x * 64;
    int tid = threadIdx.x;
    const float* gph = gp_w + (size_t)h * kGP * kHD;
    for (int i = tid; i < kGP * 16; i += 256) {
        int r = i >> 4, c4 = (i & 15) * 4;
        *(float4*)&gps[r][c4] = *(const float4*)(gph + r * kHD + c4);
    }
    const float* vb = qkv + (size_t)(b * kN + n0) * kQD + 2 * kD + h * kHD;
    for (int i = tid; i < 64 * 16; i += 256) {
        int r = i >> 4, c4 = (i & 15) * 4;
        *(float4*)&Vs[r][c4] = *(const float4*)(vb + (size_t)r * kQD + c4);
    }
    __syncthreads();
    int r = tid >> 2;
    int c0 = tid & 3;
    float val[13];
    float mx = -1e30f;
#pragma unroll
    for (int j = 0; j < 13; j++) {
        int c = c0 + 4 * j;
        float acc = 0.f;
        if (c < kGP) {
#pragma unroll
            for (int d = 0; d < kHD; d += 4) {
                float4 vv = *(const float4*)&Vs[r][d];
                float4 gg = *(const float4*)&gps[c][d];
                acc += vv.x * gg.x + vv.y * gg.y + vv.z * gg.z + vv.w * gg.w;
            }
            acc = gelu_exact(acc);
            mx = fmaxf(mx, acc);
        }
        val[j] = acc;
    }
    mx = fmaxf(mx, __shfl_xor_sync(0xffffffffu, mx, 1));
    mx = fmaxf(mx, __shfl_xor_sync(0xffffffffu, mx, 2));
    float sum = 0.f;
#pragma unroll
    for (int j = 0; j < 13; j++) {
        int c = c0 + 4 * j;
        val[j] = (c < kGP) ? __expf(val[j] - mx) : 0.f;
        sum += val[j];
    }
    sum += __shfl_xor_sync(0xffffffffu, sum, 1);
    sum += __shfl_xor_sync(0xffffffffu, sum, 2);
    float is = 1.f / sum;
    float* grow = gw + (size_t)(bh * kN + n0 + r) * 64;
#pragma unroll
    for (int j = 0; j < 16; j++) {
        int c = c0 + 4 * j;
        if (c < 64) grow[c] = (j < 13 && c < kGP) ? val[j] * is : 0.f;
    }
}

// ------- per-row: P = softmax(S*G); A = (1-a)P + a*G  (A overwrites S) -------
// float4 per thread (256 thr x 4 = 1024 cols).
__global__ __launch_bounds__(256) void rowmix_kernel(const float* __restrict__ alpha,
                                                     float* __restrict__ S,
                                                     const float* __restrict__ G) {
    __shared__ float sh1[8];
    int gr = blockIdx.x;                 // bh*N + n
    int h = (gr >> 10) % kH;
    size_t off = (size_t)gr * kN;
    int t = threadIdx.x;
    float a = 1.f / (1.f + __expf(-alpha[h]));
    float4 sv = *(const float4*)&S[off + t * 4];
    float4 gv = *(const float4*)&G[off + t * 4];
    float tv[4] = { sv.x * gv.x, sv.y * gv.y, sv.z * gv.z, sv.w * gv.w };
    float mx = fmaxf(fmaxf(tv[0], tv[1]), fmaxf(tv[2], tv[3]));
    for (int o = 16; o; o >>= 1) mx = fmaxf(mx, __shfl_xor_sync(0xffffffffu, mx, o));
    if ((t & 31) == 0) sh1[t >> 5] = mx;
    __syncthreads();
    mx = sh1[t & 7];
    for (int o = 4; o; o >>= 1) mx = fmaxf(mx, __shfl_xor_sync(0xffffffffu, mx, o));
    __syncthreads();
    float e[4], sum = 0.f;
#pragma unroll
    for (int i = 0; i < 4; i++) { e[i] = __expf(tv[i] - mx); sum += e[i]; }
    for (int o = 16; o; o >>= 1) sum += __shfl_xor_sync(0xffffffffu, sum, o);
    if ((t & 31) == 0) sh1[t >> 5] = sum;
    __syncthreads();
    sum = sh1[t & 7];
    for (int o = 4; o; o >>= 1) sum += __shfl_xor_sync(0xffffffffu, sum, o);
    float isum = (1.f - a) / sum;
    float4 o4;
    o4.x = e[0] * isum + a * gv.x;
    o4.y = e[1] * isum + a * gv.y;
    o4.z = e[2] * isum + a * gv.z;
    o4.w = e[3] * isum + a * gv.w;
    *(float4*)&S[off + t * 4] = o4;
}

// ------- column sums over n (axis=2), stores 1/(sum+1e-8) -------
// 8 independent accumulator chains for MLP.
__global__ __launch_bounds__(256) void colsum_kernel(const float* __restrict__ Sa,
                                                     float* __restrict__ inv) {
    int idx = blockIdx.x * 256 + threadIdx.x;   // bh*N + m
    int bh = idx >> 10, m = idx & 1023;
    const float* p = Sa + (size_t)bh * kN * kN + m;
    float s0 = 0.f, s1 = 0.f, s2 = 0.f, s3 = 0.f;
    float s4 = 0.f, s5 = 0.f, s6 = 0.f, s7 = 0.f;
#pragma unroll 4
    for (int n = 0; n < kN; n += 8) {
        s0 += p[(size_t)(n + 0) * kN];
        s1 += p[(size_t)(n + 1) * kN];
        s2 += p[(size_t)(n + 2) * kN];
        s3 += p[(size_t)(n + 3) * kN];
        s4 += p[(size_t)(n + 4) * kN];
        s5 += p[(size_t)(n + 5) * kN];
        s6 += p[(size_t)(n + 6) * kN];
        s7 += p[(size_t)(n + 7) * kN];
    }
    float s = ((s0 + s1) + (s2 + s3)) + ((s4 + s5) + (s6 + s7));
    inv[idx] = 1.f / (s + 1e-8f);
}

// ---------------- launch ----------------
extern "C" void kernel_launch(void* const* d_in, const int* in_sizes, int n_in,
                              void* d_out, int out_size) {
    const float* x      = (const float*)d_in[0];
    const float* ln1_w  = (const float*)d_in[1];
    const float* ln1_b  = (const float*)d_in[2];
    const float* qkv_w  = (const float*)d_in[3];
    const float* qkv_b  = (const float*)d_in[4];
    const float* proj_w = (const float*)d_in[5];
    const float* proj_b = (const float*)d_in[6];
    const float* gp_w   = (const float*)d_in[7];
    const float* alpha  = (const float*)d_in[8];
    const float* ln2_w  = (const float*)d_in[9];
    const float* ln2_b  = (const float*)d_in[10];
    const float* ff1_w  = (const float*)d_in[11];
    const float* ff1_b  = (const float*)d_in[12];
    const float* ff2_w  = (const float*)d_in[13];
    const float* ff2_b  = (const float*)d_in[14];
    float* out = (float*)d_out;

    float *xn, *qkv, *S, *G, *gw, *inv, *ctx, *y, *yn, *hdn;
    cudaGetSymbolAddress((void**)&xn,  g_xn);
    cudaGetSymbolAddress((void**)&qkv, g_qkv);
    cudaGetSymbolAddress((void**)&S,   g_S);
    cudaGetSymbolAddress((void**)&G,   g_G);
    cudaGetSymbolAddress((void**)&gw,  g_gw);
    cudaGetSymbolAddress((void**)&inv, g_inv);
    cudaGetSymbolAddress((void**)&ctx, g_ctx);
    cudaGetSymbolAddress((void**)&y,   g_y);
    cudaGetSymbolAddress((void**)&yn,  g_yn);
    cudaGetSymbolAddress((void**)&hdn, g_hdn);

    // attention branch
    ln_kernel<<<kT, 256>>>(x, ln1_w, ln1_b, xn);
    gemm_nn_tf32<<<dim3(kQD / 128, kT / 128), 256>>>(xn, qkv_w, qkv_b, nullptr,
                                                     qkv, kT, kQD, kD, 0);
    score_tf32<<<dim3(8, 8, kBH), 256>>>(qkv, S);
    gw_kernel<<<dim3(kN / 64, kBH), 256>>>(qkv, gp_w, gw);
    gmat_tf32<<<dim3(8, 8, kBH), 256>>>(gw, G);
    rowmix_kernel<<<kBH * kN, 256>>>(alpha, S, G);
    colsum_kernel<<<kBH * kN / 256, 256>>>(S, inv);
    av_tf32<<<dim3(1, 8, kBH), 256>>>(S, inv, qkv, ctx);
    gemm_nn_tf32<<<dim3(kD / 128, kT / 128), 256>>>(ctx, proj_w, proj_b, x, y,
                                                    kT, kD, kD, 0);
    // FFN branch
    ln_kernel<<<kT, 256>>>(y, ln2_w, ln2_b, yn);
    gemm_nn_tf32<<<dim3(kMLP / 128, kT / 128), 256>>>(yn, ff1_w, ff1_b, nullptr,
                                                      hdn, kT, kMLP, kD, 1);
    gemm_nn_tf32<<<dim3(kD / 128, kT / 128), 256>>>(hdn, ff2_w, ff2_b, y, out,
                                                    kT, kD, kMLP, 0);
}

// round 8
// speedup vs baseline: 1.4080x; 1.0828x over previous
#include <cuda_runtime.h>
#include <math.h>
#include <stdint.h>

// ---------------- problem constants ----------------
namespace {
constexpr int kB  = 4;
constexpr int kN  = 1024;
constexpr int kD  = 768;
constexpr int kH  = 12;
constexpr int kHD = 64;
constexpr int kGP = 49;
constexpr int kMLP = 3072;
constexpr int kT  = kB * kN;     // 4096 tokens
constexpr int kBH = kB * kH;     // 48 batched heads
constexpr int kQD = 3 * kD;      // 2304
// gemm dynamic smem: 3 stages of (As 128x20 + Bs 16x136) uint32
constexpr int kGemmSmem = 3 * (128 * 20 + 16 * 136) * 4;
}

// ---------------- scratch (device globals: no allocation allowed) ----------------
__device__ float g_xn [kT * kD];
__device__ float g_qkv[kT * kQD];
__device__ float g_S  [(size_t)kBH * kN * kN];   // scores, later the mixed attn A
__device__ float g_G  [(size_t)kBH * kN * kN];   // gw @ gw^T
__device__ float g_gw [kBH * kN * 64];           // softmaxed group weights, padded 49->64
__device__ float g_inv[kBH * kN];                // 1/(colsum+eps)
__device__ float g_vs [kBH * kN * kHD];          // inv-scaled V, contiguous per head
__device__ float g_ctx[kT * kD];                 // merged-head attention output
__device__ float g_y  [kT * kD];                 // after proj residual
__device__ float g_yn [kT * kD];
__device__ float g_hdn[kT * kMLP];

__device__ __forceinline__ float gelu_exact(float x) {
    return 0.5f * x * (1.0f + erff(x * 0.70710678118654752440f));
}

__device__ __forceinline__ uint32_t f2tf32(float x) {
    uint32_t r;
    asm("cvt.rna.tf32.f32 %0, %1;" : "=r"(r) : "f"(x));
    return r;
}

__device__ __forceinline__ void cp16(void* dst_smem, const void* src_gmem) {
    uint32_t d = (uint32_t)__cvta_generic_to_shared(dst_smem);
    asm volatile("cp.async.cg.shared.global [%0], [%1], 16;" :: "r"(d), "l"(src_gmem));
}
__device__ __forceinline__ void cp_commit() {
    asm volatile("cp.async.commit_group;");
}
__device__ __forceinline__ void cp_wait1() {
    asm volatile("cp.async.wait_group 1;");
}

// D += A(m16k8,row) * B(k8n8,col)   tf32
__device__ __forceinline__ void mma8(float* c, const uint32_t* a, const uint32_t* b) {
    asm volatile("mma.sync.aligned.m16n8k8.row.col.f32.tf32.tf32.f32 "
                 "{%0,%1,%2,%3}, {%4,%5,%6,%7}, {%8,%9}, {%0,%1,%2,%3};"
                 : "+f"(c[0]), "+f"(c[1]), "+f"(c[2]), "+f"(c[3])
                 : "r"(a[0]), "r"(a[1]), "r"(a[2]), "r"(a[3]),
                   "r"(b[0]), "r"(b[1]));
}

// ---------------- LayerNorm: one block (256 thr) per row of 768 ----------------
__global__ __launch_bounds__(256) void ln_kernel(const float* __restrict__ x,
                                                 const float* __restrict__ w,
                                                 const float* __restrict__ b,
                                                 float* __restrict__ out) {
    __shared__ float sh1[8], sh2[8];
    int row = blockIdx.x;
    int t = threadIdx.x;
    const float* xr = x + (size_t)row * kD;
    float v[3];
    float s = 0.f, s2 = 0.f;
#pragma unroll
    for (int i = 0; i < 3; i++) {
        v[i] = xr[t + i * 256];
        s  += v[i];
        s2 += v[i] * v[i];
    }
#pragma unroll
    for (int o = 16; o; o >>= 1) {
        s  += __shfl_xor_sync(0xffffffffu, s, o);
        s2 += __shfl_xor_sync(0xffffffffu, s2, o);
    }
    if ((t & 31) == 0) { sh1[t >> 5] = s; sh2[t >> 5] = s2; }
    __syncthreads();
    s = sh1[t & 7]; s2 = sh2[t & 7];
#pragma unroll
    for (int o = 4; o; o >>= 1) {
        s  += __shfl_xor_sync(0xffffffffu, s, o);
        s2 += __shfl_xor_sync(0xffffffffu, s2, o);
    }
    float mu   = s * (1.0f / kD);
    float var  = fmaxf(s2 * (1.0f / kD) - mu * mu, 0.f);
    float rstd = rsqrtf(var + 1e-5f);
    float* orow = out + (size_t)row * kD;
#pragma unroll
    for (int i = 0; i < 3; i++) {
        int c = t + i * 256;
        orow[c] = (v[i] - mu) * rstd * w[c] + b[c];
    }
}

// ------- TF32 dense GEMM (NN): C = A@B + bias (+gelu)(+res) -------------------
// 128x128 block, 8 warps, warp m32 x n64, K-step 16, 3-stage cp.async pipeline.
// smem holds raw fp32 bits; mma consumes them as tf32 (truncation).
__global__ __launch_bounds__(256) void gemm_nn_tf32(
        const float* __restrict__ A, const float* __restrict__ B,
        const float* __restrict__ bias, const float* __restrict__ res,
        float* __restrict__ C, int M, int N, int K, int act) {
    extern __shared__ uint32_t dsm[];
    uint32_t* AsBuf = dsm;                      // [3][128*20]
    uint32_t* BsBuf = dsm + 3 * 128 * 20;       // [3][16*136]
#define GAS(s, r, c) AsBuf[(s) * 2560 + (r) * 20 + (c)]
#define GBS(s, r, c) BsBuf[(s) * 2176 + (r) * 136 + (c)]
    int tid = threadIdx.x, lane = tid & 31, warp = tid >> 5;
    int g = lane >> 2, tg = lane & 3;
    int wm = (warp >> 1) * 32, wn = (warp & 1) * 64;
    int row0 = blockIdx.y * 128, col0 = blockIdx.x * 128;
    int ra = tid >> 2, ca = (tid & 3) * 4;       // A loader coords
    int kb = tid >> 5, nb = (tid & 31) * 4;      // B loader coords
    const float* Abase  = A + (size_t)(row0 + ra) * K + ca;
    const float* Abase2 = A + (size_t)(row0 + ra + 64) * K + ca;
    const float* Bbase  = B + (size_t)kb * N + col0 + nb;
    const float* Bbase2 = B + (size_t)(kb + 8) * N + col0 + nb;
    float acc[2][8][4] = {};

    auto issue = [&](int k0, int s) {
        if (k0 < K) {
            cp16(&GAS(s, ra, ca),      Abase + k0);
            cp16(&GAS(s, ra + 64, ca), Abase2 + k0);
            cp16(&GBS(s, kb, nb),      Bbase + (size_t)k0 * N);
            cp16(&GBS(s, kb + 8, nb),  Bbase2 + (size_t)k0 * N);
        }
        cp_commit();
    };
    issue(0, 0);
    issue(16, 1);
    int s = 0;
    for (int k0 = 0; k0 < K; k0 += 16) {
        cp_wait1();
        __syncthreads();
        int s2n = s + 2 >= 3 ? s - 1 : s + 2;
        issue(k0 + 32, s2n);
#pragma unroll
        for (int k8 = 0; k8 < 16; k8 += 8) {
            uint32_t af[2][4], bf[8][2];
#pragma unroll
            for (int mi = 0; mi < 2; mi++) {
                int r = wm + mi * 16 + g;
                af[mi][0] = GAS(s, r, k8 + tg);
                af[mi][1] = GAS(s, r + 8, k8 + tg);
                af[mi][2] = GAS(s, r, k8 + tg + 4);
                af[mi][3] = GAS(s, r + 8, k8 + tg + 4);
            }
#pragma unroll
            for (int nj = 0; nj < 8; nj++) {
                int n = wn + nj * 8 + g;
                bf[nj][0] = GBS(s, k8 + tg, n);
                bf[nj][1] = GBS(s, k8 + tg + 4, n);
            }
#pragma unroll
            for (int mi = 0; mi < 2; mi++)
#pragma unroll
                for (int nj = 0; nj < 8; nj++)
                    mma8(acc[mi][nj], af[mi], bf[nj]);
        }
        s = s + 1 >= 3 ? 0 : s + 1;
    }
#undef GAS
#undef GBS
#pragma unroll
    for (int mi = 0; mi < 2; mi++) {
#pragma unroll
        for (int nj = 0; nj < 8; nj++) {
            int r0 = row0 + wm + mi * 16 + g;
            int c = col0 + wn + nj * 8 + tg * 2;
            float b0 = bias[c], b1 = bias[c + 1];
            float o00 = acc[mi][nj][0] + b0, o01 = acc[mi][nj][1] + b1;
            float o10 = acc[mi][nj][2] + b0, o11 = acc[mi][nj][3] + b1;
            if (act) {
                o00 = gelu_exact(o00); o01 = gelu_exact(o01);
                o10 = gelu_exact(o10); o11 = gelu_exact(o11);
            }
            if (res) {
                o00 += res[(size_t)r0 * N + c];       o01 += res[(size_t)r0 * N + c + 1];
                o10 += res[(size_t)(r0 + 8) * N + c]; o11 += res[(size_t)(r0 + 8) * N + c + 1];
            }
            *(float2*)&C[(size_t)r0 * N + c]       = make_float2(o00, o01);
            *(float2*)&C[(size_t)(r0 + 8) * N + c] = make_float2(o10, o11);
        }
    }
}

// ---------------- scores S = scale * Q @ K^T (NT), tf32, batched over BH ------
__global__ __launch_bounds__(256) void score_tf32(const float* __restrict__ qkv,
                                                  float* __restrict__ S) {
    __shared__ uint32_t As[128][20];
    __shared__ uint32_t Bs[128][20];
    int bh = blockIdx.z, b = bh / kH, h = bh % kH;
    const float* qb = qkv + (size_t)b * kN * kQD + h * kHD;
    const float* kb = qb + kD;
    int tid = threadIdx.x, lane = tid & 31, warp = tid >> 5;
    int g = lane >> 2, tg = lane & 3;
    int wm = (warp >> 1) * 32, wn = (warp & 1) * 64;
    int n0 = blockIdx.y * 128, m0 = blockIdx.x * 128;
    int ra = tid >> 2, ca = (tid & 3) * 4;
    const float* Qp0 = qb + (size_t)(n0 + ra) * kQD + ca;
    const float* Qp1 = Qp0 + (size_t)64 * kQD;
    const float* Kp0 = kb + (size_t)(m0 + ra) * kQD + ca;
    const float* Kp1 = Kp0 + (size_t)64 * kQD;
    float acc[2][8][4] = {};
    float4 q0 = *(const float4*)Qp0, q1 = *(const float4*)Qp1;
    float4 v0 = *(const float4*)Kp0, v1 = *(const float4*)Kp1;
    for (int k0 = 0; k0 < kHD; k0 += 16) {
        As[ra][ca + 0] = f2tf32(q0.x); As[ra][ca + 1] = f2tf32(q0.y);
        As[ra][ca + 2] = f2tf32(q0.z); As[ra][ca + 3] = f2tf32(q0.w);
        As[ra + 64][ca + 0] = f2tf32(q1.x); As[ra + 64][ca + 1] = f2tf32(q1.y);
        As[ra + 64][ca + 2] = f2tf32(q1.z); As[ra + 64][ca + 3] = f2tf32(q1.w);
        Bs[ra][ca + 0] = f2tf32(v0.x); Bs[ra][ca + 1] = f2tf32(v0.y);
        Bs[ra][ca + 2] = f2tf32(v0.z); Bs[ra][ca + 3] = f2tf32(v0.w);
        Bs[ra + 64][ca + 0] = f2tf32(v1.x); Bs[ra + 64][ca + 1] = f2tf32(v1.y);
        Bs[ra + 64][ca + 2] = f2tf32(v1.z); Bs[ra + 64][ca + 3] = f2tf32(v1.w);
        __syncthreads();
        if (k0 + 16 < kHD) {
            q0 = *(const float4*)(Qp0 + k0 + 16);
            q1 = *(const float4*)(Qp1 + k0 + 16);
            v0 = *(const float4*)(Kp0 + k0 + 16);
            v1 = *(const float4*)(Kp1 + k0 + 16);
        }
#pragma unroll
        for (int k8 = 0; k8 < 16; k8 += 8) {
            uint32_t af[2][4], bf[8][2];
#pragma unroll
            for (int mi = 0; mi < 2; mi++) {
                int r = wm + mi * 16 + g;
                af[mi][0] = As[r][k8 + tg];
                af[mi][1] = As[r + 8][k8 + tg];
                af[mi][2] = As[r][k8 + tg + 4];
                af[mi][3] = As[r + 8][k8 + tg + 4];
            }
#pragma unroll
            for (int nj = 0; nj < 8; nj++) {
                int n = wn + nj * 8 + g;
                bf[nj][0] = Bs[n][k8 + tg];
                bf[nj][1] = Bs[n][k8 + tg + 4];
            }
#pragma unroll
            for (int mi = 0; mi < 2; mi++)
#pragma unroll
                for (int nj = 0; nj < 8; nj++)
                    mma8(acc[mi][nj], af[mi], bf[nj]);
        }
        __syncthreads();
    }
    float* Sb = S + (size_t)bh * kN * kN;
#pragma unroll
    for (int mi = 0; mi < 2; mi++) {
#pragma unroll
        for (int nj = 0; nj < 8; nj++) {
            int r0 = n0 + wm + mi * 16 + g;
            int c = m0 + wn + nj * 8 + tg * 2;
            *(float2*)&Sb[(size_t)r0 * kN + c] =
                make_float2(acc[mi][nj][0] * 0.125f, acc[mi][nj][1] * 0.125f);
            *(float2*)&Sb[(size_t)(r0 + 8) * kN + c] =
                make_float2(acc[mi][nj][2] * 0.125f, acc[mi][nj][3] * 0.125f);
        }
    }
}

// ---------------- G = gw @ gw^T (NT), tf32, K=64 padded ----------------
__global__ __launch_bounds__(256) void gmat_tf32(const float* __restrict__ gw,
                                                 float* __restrict__ G) {
    __shared__ uint32_t As[128][20];
    __shared__ uint32_t Bs[128][20];
    int bh = blockIdx.z;
    const float* gb = gw + (size_t)bh * kN * 64;
    int tid = threadIdx.x, lane = tid & 31, warp = tid >> 5;
    int g = lane >> 2, tg = lane & 3;
    int wm = (warp >> 1) * 32, wn = (warp & 1) * 64;
    int n0 = blockIdx.y * 128, m0 = blockIdx.x * 128;
    int ra = tid >> 2, ca = (tid & 3) * 4;
    const float* Ap0 = gb + (size_t)(n0 + ra) * 64 + ca;
    const float* Ap1 = Ap0 + (size_t)64 * 64;
    const float* Bp0 = gb + (size_t)(m0 + ra) * 64 + ca;
    const float* Bp1 = Bp0 + (size_t)64 * 64;
    float acc[2][8][4] = {};
    float4 a0 = *(const float4*)Ap0, a1 = *(const float4*)Ap1;
    float4 b0 = *(const float4*)Bp0, b1 = *(const float4*)Bp1;
    for (int k0 = 0; k0 < 64; k0 += 16) {
        As[ra][ca + 0] = f2tf32(a0.x); As[ra][ca + 1] = f2tf32(a0.y);
        As[ra][ca + 2] = f2tf32(a0.z); As[ra][ca + 3] = f2tf32(a0.w);
        As[ra + 64][ca + 0] = f2tf32(a1.x); As[ra + 64][ca + 1] = f2tf32(a1.y);
        As[ra + 64][ca + 2] = f2tf32(a1.z); As[ra + 64][ca + 3] = f2tf32(a1.w);
        Bs[ra][ca + 0] = f2tf32(b0.x); Bs[ra][ca + 1] = f2tf32(b0.y);
        Bs[ra][ca + 2] = f2tf32(b0.z); Bs[ra][ca + 3] = f2tf32(b0.w);
        Bs[ra + 64][ca + 0] = f2tf32(b1.x); Bs[ra + 64][ca + 1] = f2tf32(b1.y);
        Bs[ra + 64][ca + 2] = f2tf32(b1.z); Bs[ra + 64][ca + 3] = f2tf32(b1.w);
        __syncthreads();
        if (k0 + 16 < 64) {
            a0 = *(const float4*)(Ap0 + k0 + 16);
            a1 = *(const float4*)(Ap1 + k0 + 16);
            b0 = *(const float4*)(Bp0 + k0 + 16);
            b1 = *(const float4*)(Bp1 + k0 + 16);
        }
#pragma unroll
        for (int k8 = 0; k8 < 16; k8 += 8) {
            uint32_t af[2][4], bf[8][2];
#pragma unroll
            for (int mi = 0; mi < 2; mi++) {
                int r = wm + mi * 16 + g;
                af[mi][0] = As[r][k8 + tg];
                af[mi][1] = As[r + 8][k8 + tg];
                af[mi][2] = As[r][k8 + tg + 4];
                af[mi][3] = As[r + 8][k8 + tg + 4];
            }
#pragma unroll
            for (int nj = 0; nj < 8; nj++) {
                int n = wn + nj * 8 + g;
                bf[nj][0] = Bs[n][k8 + tg];
                bf[nj][1] = Bs[n][k8 + tg + 4];
            }
#pragma unroll
            for (int mi = 0; mi < 2; mi++)
#pragma unroll
                for (int nj = 0; nj < 8; nj++)
                    mma8(acc[mi][nj], af[mi], bf[nj]);
        }
        __syncthreads();
    }
    float* Gb = G + (size_t)bh * kN * kN;
#pragma unroll
    for (int mi = 0; mi < 2; mi++) {
#pragma unroll
        for (int nj = 0; nj < 8; nj++) {
            int r0 = n0 + wm + mi * 16 + g;
            int c = m0 + wn + nj * 8 + tg * 2;
            *(float2*)&Gb[(size_t)r0 * kN + c] =
                make_float2(acc[mi][nj][0], acc[mi][nj][1]);
            *(float2*)&Gb[(size_t)(r0 + 8) * kN + c] =
                make_float2(acc[mi][nj][2], acc[mi][nj][3]);
        }
    }
}

// ------- vs[bh][k][d] = V[b,k,h,d] * inv[bh,k]  (contiguous per head) --------
__global__ __launch_bounds__(256) void vscale_kernel(const float* __restrict__ qkv,
                                                     const float* __restrict__ inv,
                                                     float* __restrict__ vs) {
    int idx = blockIdx.x * 256 + threadIdx.x;       // over kBH*kN*16 float4s
    int d4 = (idx & 15) * 4;
    int k  = (idx >> 4) & 1023;
    int bh = idx >> 14;
    int b = bh / kH, h = bh % kH;
    float iv = inv[bh * kN + k];
    float4 v = *(const float4*)(qkv + (size_t)(b * kN + k) * kQD + 2 * kD + h * kHD + d4);
    v.x *= iv; v.y *= iv; v.z *= iv; v.w *= iv;
    *(float4*)(vs + (size_t)bh * kN * kHD + (size_t)k * kHD + d4) = v;
}

// ------- out = A @ Vs (NN), tf32, 3-stage cp.async; heads merged into ctx -----
__global__ __launch_bounds__(256) void av_tf32(const float* __restrict__ Sa,
                                               const float* __restrict__ vs,
                                               float* __restrict__ ctx) {
    __shared__ __align__(16) uint32_t As[3][128][20];
    __shared__ __align__(16) uint32_t Bs[3][16][72];
    int bh = blockIdx.z, b = bh / kH, h = bh % kH;
    const float* Ab = Sa + (size_t)bh * kN * kN;
    const float* vb = vs + (size_t)bh * kN * kHD;
    int tid = threadIdx.x, lane = tid & 31, warp = tid >> 5;
    int g = lane >> 2, tg = lane & 3;
    int wm = (warp >> 1) * 32, wn = (warp & 1) * 32;
    int row0 = blockIdx.y * 128;
    int ra = tid >> 2, ca = (tid & 3) * 4;
    int kr = tid >> 4, nc = (tid & 15) * 4;
    const float* Ap0 = Ab + (size_t)(row0 + ra) * kN + ca;
    const float* Ap1 = Ap0 + (size_t)64 * kN;
    const float* Vp  = vb + (size_t)kr * kHD + nc;
    float acc[2][4][4] = {};
    auto issue = [&](int k0, int s) {
        if (k0 < kN) {
            cp16(&As[s][ra][ca],      Ap0 + k0);
            cp16(&As[s][ra + 64][ca], Ap1 + k0);
            cp16(&Bs[s][kr][nc],      Vp + (size_t)k0 * kHD);
        }
        cp_commit();
    };
    issue(0, 0);
    issue(16, 1);
    int s = 0;
    for (int k0 = 0; k0 < kN; k0 += 16) {
        cp_wait1();
        __syncthreads();
        int s2n = s + 2 >= 3 ? s - 1 : s + 2;
        issue(k0 + 32, s2n);
#pragma unroll
        for (int k8 = 0; k8 < 16; k8 += 8) {
            uint32_t af[2][4], bf[4][2];
#pragma unroll
            for (int mi = 0; mi < 2; mi++) {
                int r = wm + mi * 16 + g;
                af[mi][0] = As[s][r][k8 + tg];
                af[mi][1] = As[s][r + 8][k8 + tg];
                af[mi][2] = As[s][r][k8 + tg + 4];
                af[mi][3] = As[s][r + 8][k8 + tg + 4];
            }
#pragma unroll
            for (int nj = 0; nj < 4; nj++) {
                int n = wn + nj * 8 + g;
                bf[nj][0] = Bs[s][k8 + tg][n];
                bf[nj][1] = Bs[s][k8 + tg + 4][n];
            }
#pragma unroll
            for (int mi = 0; mi < 2; mi++)
#pragma unroll
                for (int nj = 0; nj < 4; nj++)
                    mma8(acc[mi][nj], af[mi], bf[nj]);
        }
        s = s + 1 >= 3 ? 0 : s + 1;
    }
#pragma unroll
    for (int mi = 0; mi < 2; mi++) {
#pragma unroll
        for (int nj = 0; nj < 4; nj++) {
            int tok0 = b * kN + row0 + wm + mi * 16 + g;
            int c = h * kHD + wn + nj * 8 + tg * 2;
            *(float2*)&ctx[(size_t)tok0 * kD + c] =
                make_float2(acc[mi][nj][0], acc[mi][nj][1]);
            *(float2*)&ctx[(size_t)(tok0 + 8) * kD + c] =
                make_float2(acc[mi][nj][2], acc[mi][nj][3]);
        }
    }
}

// ---- group weights: gw = softmax(gelu(V @ gp^T)) padded to 64 ----
__global__ __launch_bounds__(256) void gw_kernel(const float* __restrict__ qkv,
                                                 const float* __restrict__ gp_w,
                                                 float* __restrict__ gw) {
    __shared__ __align__(16) float gps[kGP][68];
    __shared__ __align__(16) float Vs[64][68];
    int bh = blockIdx.y;
    int b = bh / kH, h = bh % kH;
    int n0 = blockIdx.x * 64;
    int tid = threadIdx.x;
    const float* gph = gp_w + (size_t)h * kGP * kHD;
    for (int i = tid; i < kGP * 16; i += 256) {
        int r = i >> 4, c4 = (i & 15) * 4;
        *(float4*)&gps[r][c4] = *(const float4*)(gph + r * kHD + c4);
    }
    const float* vb = qkv + (size_t)(b * kN + n0) * kQD + 2 * kD + h * kHD;
    for (int i = tid; i < 64 * 16; i += 256) {
        int r = i >> 4, c4 = (i & 15) * 4;
        *(float4*)&Vs[r][c4] = *(const float4*)(vb + (size_t)r * kQD + c4);
    }
    __syncthreads();
    int r = tid >> 2;
    int c0 = tid & 3;
    float val[13];
    float mx = -1e30f;
#pragma unroll
    for (int j = 0; j < 13; j++) {
        int c = c0 + 4 * j;
        float acc = 0.f;
        if (c < kGP) {
#pragma unroll
            for (int d = 0; d < kHD; d += 4) {
                float4 vv = *(const float4*)&Vs[r][d];
                float4 gg = *(const float4*)&gps[c][d];
                acc += vv.x * gg.x + vv.y * gg.y + vv.z * gg.z + vv.w * gg.w;
            }
            acc = gelu_exact(acc);
            mx = fmaxf(mx, acc);
        }
        val[j] = acc;
    }
    mx = fmaxf(mx, __shfl_xor_sync(0xffffffffu, mx, 1));
    mx = fmaxf(mx, __shfl_xor_sync(0xffffffffu, mx, 2));
    float sum = 0.f;
#pragma unroll
    for (int j = 0; j < 13; j++) {
        int c = c0 + 4 * j;
        val[j] = (c < kGP) ? __expf(val[j] - mx) : 0.f;
        sum += val[j];
    }
    sum += __shfl_xor_sync(0xffffffffu, sum, 1);
    sum += __shfl_xor_sync(0xffffffffu, sum, 2);
    float is = 1.f / sum;
    float* grow = gw + (size_t)(bh * kN + n0 + r) * 64;
#pragma unroll
    for (int j = 0; j < 16; j++) {
        int c = c0 + 4 * j;
        if (c < 64) grow[c] = (j < 13 && c < kGP) ? val[j] * is : 0.f;
    }
}

// ------- per-row: P = softmax(S*G); A = (1-a)P + a*G  (A overwrites S) -------
__global__ __launch_bounds__(256) void rowmix_kernel(const float* __restrict__ alpha,
                                                     float* __restrict__ S,
                                                     const float* __restrict__ G) {
    __shared__ float sh1[8];
    int gr = blockIdx.x;                 // bh*N + n
    int h = (gr >> 10) % kH;
    size_t off = (size_t)gr * kN;
    int t = threadIdx.x;
    float a = 1.f / (1.f + __expf(-alpha[h]));
    float4 sv = *(const float4*)&S[off + t * 4];
    float4 gv = *(const float4*)&G[off + t * 4];
    float tv[4] = { sv.x * gv.x, sv.y * gv.y, sv.z * gv.z, sv.w * gv.w };
    float mx = fmaxf(fmaxf(tv[0], tv[1]), fmaxf(tv[2], tv[3]));
    for (int o = 16; o; o >>= 1) mx = fmaxf(mx, __shfl_xor_sync(0xffffffffu, mx, o));
    if ((t & 31) == 0) sh1[t >> 5] = mx;
    __syncthreads();
    mx = sh1[t & 7];
    for (int o = 4; o; o >>= 1) mx = fmaxf(mx, __shfl_xor_sync(0xffffffffu, mx, o));
    __syncthreads();
    float e[4], sum = 0.f;
#pragma unroll
    for (int i = 0; i < 4; i++) { e[i] = __expf(tv[i] - mx); sum += e[i]; }
    for (int o = 16; o; o >>= 1) sum += __shfl_xor_sync(0xffffffffu, sum, o);
    if ((t & 31) == 0) sh1[t >> 5] = sum;
    __syncthreads();
    sum = sh1[t & 7];
    for (int o = 4; o; o >>= 1) sum += __shfl_xor_sync(0xffffffffu, sum, o);
    float isum = (1.f - a) / sum;
    float4 o4;
    o4.x = e[0] * isum + a * gv.x;
    o4.y = e[1] * isum + a * gv.y;
    o4.z = e[2] * isum + a * gv.z;
    o4.w = e[3] * isum + a * gv.w;
    *(float4*)&S[off + t * 4] = o4;
}

// ------- column sums over n (axis=2), stores 1/(sum+1e-8) -------
__global__ __launch_bounds__(256) void colsum_kernel(const float* __restrict__ Sa,
                                                     float* __restrict__ inv) {
    int idx = blockIdx.x * 256 + threadIdx.x;   // bh*N + m
    int bh = idx >> 10, m = idx & 1023;
    const float* p = Sa + (size_t)bh * kN * kN + m;
    float s0 = 0.f, s1 = 0.f, s2 = 0.f, s3 = 0.f;
    float s4 = 0.f, s5 = 0.f, s6 = 0.f, s7 = 0.f;
#pragma unroll 4
    for (int n = 0; n < kN; n += 8) {
        s0 += p[(size_t)(n + 0) * kN];
        s1 += p[(size_t)(n + 1) * kN];
        s2 += p[(size_t)(n + 2) * kN];
        s3 += p[(size_t)(n + 3) * kN];
        s4 += p[(size_t)(n + 4) * kN];
        s5 += p[(size_t)(n + 5) * kN];
        s6 += p[(size_t)(n + 6) * kN];
        s7 += p[(size_t)(n + 7) * kN];
    }
    float s = ((s0 + s1) + (s2 + s3)) + ((s4 + s5) + (s6 + s7));
    inv[idx] = 1.f / (s + 1e-8f);
}

// ---------------- launch ----------------
extern "C" void kernel_launch(void* const* d_in, const int* in_sizes, int n_in,
                              void* d_out, int out_size) {
    const float* x      = (const float*)d_in[0];
    const float* ln1_w  = (const float*)d_in[1];
    const float* ln1_b  = (const float*)d_in[2];
    const float* qkv_w  = (const float*)d_in[3];
    const float* qkv_b  = (const float*)d_in[4];
    const float* proj_w = (const float*)d_in[5];
    const float* proj_b = (const float*)d_in[6];
    const float* gp_w   = (const float*)d_in[7];
    const float* alpha  = (const float*)d_in[8];
    const float* ln2_w  = (const float*)d_in[9];
    const float* ln2_b  = (const float*)d_in[10];
    const float* ff1_w  = (const float*)d_in[11];
    const float* ff1_b  = (const float*)d_in[12];
    const float* ff2_w  = (const float*)d_in[13];
    const float* ff2_b  = (const float*)d_in[14];
    float* out = (float*)d_out;

    float *xn, *qkv, *S, *G, *gw, *inv, *vs, *ctx, *y, *yn, *hdn;
    cudaGetSymbolAddress((void**)&xn,  g_xn);
    cudaGetSymbolAddress((void**)&qkv, g_qkv);
    cudaGetSymbolAddress((void**)&S,   g_S);
    cudaGetSymbolAddress((void**)&G,   g_G);
    cudaGetSymbolAddress((void**)&gw,  g_gw);
    cudaGetSymbolAddress((void**)&inv, g_inv);
    cudaGetSymbolAddress((void**)&vs,  g_vs);
    cudaGetSymbolAddress((void**)&ctx, g_ctx);
    cudaGetSymbolAddress((void**)&y,   g_y);
    cudaGetSymbolAddress((void**)&yn,  g_yn);
    cudaGetSymbolAddress((void**)&hdn, g_hdn);

    cudaFuncSetAttribute(gemm_nn_tf32,
                         cudaFuncAttributeMaxDynamicSharedMemorySize, kGemmSmem);

    // attention branch
    ln_kernel<<<kT, 256>>>(x, ln1_w, ln1_b, xn);
    gemm_nn_tf32<<<dim3(kQD / 128, kT / 128), 256, kGemmSmem>>>(
        xn, qkv_w, qkv_b, nullptr, qkv, kT, kQD, kD, 0);
    score_tf32<<<dim3(8, 8, kBH), 256>>>(qkv, S);
    gw_kernel<<<dim3(kN / 64, kBH), 256>>>(qkv, gp_w, gw);
    gmat_tf32<<<dim3(8, 8, kBH), 256>>>(gw, G);
    rowmix_kernel<<<kBH * kN, 256>>>(alpha, S, G);
    colsum_kernel<<<kBH * kN / 256, 256>>>(S, inv);
    vscale_kernel<<<kBH * kN * 16 / 256, 256>>>(qkv, inv, vs);
    av_tf32<<<dim3(1, 8, kBH), 256>>>(S, vs, ctx);
    gemm_nn_tf32<<<dim3(kD / 128, kT / 128), 256, kGemmSmem>>>(
        ctx, proj_w, proj_b, x, y, kT, kD, kD, 0);
    // FFN branch
    ln_kernel<<<kT, 256>>>(y, ln2_w, ln2_b, yn);
    gemm_nn_tf32<<<dim3(kMLP / 128, kT / 128), 256, kGemmSmem>>>(
        yn, ff1_w, ff1_b, nullptr, hdn, kT, kMLP, kD, 1);
    gemm_nn_tf32<<<dim3(kD / 128, kT / 128), 256, kGemmSmem>>>(
        hdn, ff2_w, ff2_b, y, out, kT, kD, kMLP, 0);
}